// round 8
// baseline (speedup 1.0000x reference)
#include <cuda_runtime.h>
#include <math.h>
#include <stdint.h>

// ---------------------------------------------------------------------------
// TriplaneDecoder via int8 double-digit mma.sync (m16n8k32.s8) — compute_100.
// x = s*(d1*128 + d0). D = sa*sb*(16384*S11 + 128*(S1m)) with
// S11 = d1a.d1b, S1m = d1a.d0b + d0a.d1b  (d0a.d0b dropped).
// CTA = 64 points, 8 warps 2(M)x4(N), warp tile 32x64, K chunked by 32.
// R8: __launch_bounds__(256, 2) -> 2 CTAs/SM (192.6KB smem) so one CTA's
// MMAs overlap the other's barriers/epilogue — fills the 26% issue gap.
// ---------------------------------------------------------------------------

#define BB 4
#define NN 100000
#define CC 64
#define HH 256
#define WW 256
#define PTS 64
#define NTH 256
#define NCHUNK_TOT 78     // L0: 6 chunks (K=192), L1..9: 8 chunks

// smem byte offsets
#define SO_A1    0        // A d1 plane: 64 x 256 s8 (16KB)
#define SO_A0    16384    // A d0 plane (16KB)
#define SO_WBUF  32768    // 2 x 16KB weight chunk buffers (d1 8KB | d0 8KB)
#define SO_ACT   0        // overlay (final f32 acts 64x256 = 64KB)
#define SO_SBIAS 65536    // biases 10*256 f32
#define SO_SB    75776    // weight col scales 10*256 f32
#define SO_WHT   86016    // head weights [256][8] f32
#define SO_RMAX  94208    // rowmax partials [64][4] f32
#define SO_SA    95232    // A row scales, ping-pong [2][64] f32
#define SO_INV   95744    // inv scale [64] f32
#define SO_FAMAX 96000    // feat |max| bits [64] u32
#define SO_BHD   96256    // head biases [8]
#define SMEM_TOT 96288

__device__ float g_trip[(size_t)BB * 3 * HH * WW * CC];
__device__ uint4 g_wq[2555904 / 16];       // quantized blocked weight chunks
__device__ float g_sb[10 * 256];           // per-output weight scales

// ---- PTX helpers -----------------------------------------------------------
__device__ __forceinline__ uint32_t smem_u32(const void* p) {
    uint32_t a;
    asm("{ .reg .u64 t; cvta.to.shared.u64 t, %1; cvt.u32.u64 %0, t; }" : "=r"(a) : "l"(p));
    return a;
}
__device__ __forceinline__ void ldsm4(uint32_t* r, uint32_t a) {
    asm volatile("ldmatrix.sync.aligned.m8n8.x4.shared.b16 {%0,%1,%2,%3}, [%4];"
                 : "=r"(r[0]), "=r"(r[1]), "=r"(r[2]), "=r"(r[3]) : "r"(a));
}
__device__ __forceinline__ void mma_s8(int* c, const uint32_t* a, uint32_t b0, uint32_t b1) {
    asm volatile("mma.sync.aligned.m16n8k32.row.col.s32.s8.s8.s32 "
                 "{%0,%1,%2,%3}, {%4,%5,%6,%7}, {%8,%9}, {%0,%1,%2,%3};"
                 : "+r"(c[0]), "+r"(c[1]), "+r"(c[2]), "+r"(c[3])
                 : "r"(a[0]), "r"(a[1]), "r"(a[2]), "r"(a[3]), "r"(b0), "r"(b1));
}
#define CP_ASYNC16(dst, src) \
    asm volatile("cp.async.cg.shared.global [%0], [%1], 16;" :: "r"(dst), "l"(src))
#define CP_COMMIT() asm volatile("cp.async.commit_group;")
#define CP_WAIT0()  asm volatile("cp.async.wait_group 0;")

// ---------------- prolog 1: triplane [pl][C][HW] -> [pl][HW][C] -------------
__global__ void transpose_trip(const float* __restrict__ in) {
    __shared__ float s[64][33];
    const int plane = blockIdx.y;
    const int hw0 = blockIdx.x * 32;
    const float* ip = in + (size_t)plane * CC * HH * WW;
    float* op = g_trip + (size_t)plane * HH * WW * CC;
    const int t = threadIdx.x, l32 = t & 31, grp = t >> 5;
#pragma unroll
    for (int i = 0; i < 8; i++) {
        int c = grp + i * 8;
        s[c][l32] = ip[(size_t)c * (HH * WW) + hw0 + l32];
    }
    __syncthreads();
    const int c2 = t & 63, r0 = t >> 6;
#pragma unroll
    for (int j = 0; j < 8; j++) {
        int r = r0 + j * 4;
        op[(size_t)(hw0 + r) * CC + c2] = s[c2][r];
    }
}

// ---------------- prolog 2: weight quantization -----------------------------
// one warp per (L, n). chunk layout (16KB = d1 8KB | d0 8KB):
//   plane offset = ((n>>3)*2 + ((k>>4)&1))*128 + (n&7)*16 + (k&15)
__global__ void prep_weights(const float* __restrict__ w_in,
                             const float* __restrict__ w_hid) {
    const int lane = threadIdx.x & 31;
    const int id = blockIdx.x * 8 + (threadIdx.x >> 5);
    if (id >= 2560) return;
    const int L = id >> 8, n = id & 255;
    const int K = (L == 0) ? 192 : 256;
    const size_t lbase = (L == 0) ? 0u : (98304u + (size_t)(L - 1) * 131072u);
    float vals[8];
    float m = 0.0f;
#pragma unroll
    for (int j = 0; j < 8; j++) {
        const int k = lane + j * 32;
        float v = 0.0f;
        if (k < K)
            v = (L == 0) ? w_in[n * 192 + k] : w_hid[(size_t)(L - 1) * 65536 + n * 256 + k];
        vals[j] = v;
        m = fmaxf(m, fabsf(v));
    }
#pragma unroll
    for (int off = 16; off; off >>= 1) m = fmaxf(m, __shfl_xor_sync(0xFFFFFFFFu, m, off));
    const float inv = 16256.0f / fmaxf(m, 1e-30f);
    int8_t* gw = (int8_t*)g_wq;
#pragma unroll
    for (int j = 0; j < 8; j++) {
        const int k = lane + j * 32;
        if (k >= K) break;
        const float q = vals[j] * inv;
        const float d1f = rintf(q * 0.0078125f);
        const int d0 = __float2int_rn(q - 128.0f * d1f);
        const int d1 = (int)d1f;
        const size_t a = lbase + (size_t)(k >> 5) * 16384
                       + (size_t)(((n >> 3) * 2 + ((k >> 4) & 1)) * 128 + (n & 7) * 16 + (k & 15));
        gw[a] = (int8_t)d1;
        gw[a + 8192] = (int8_t)d0;
    }
    if (lane == 0) g_sb[id] = m * (1.0f / 16256.0f);
}

// ---------------- main fused decoder ----------------------------------------
__global__ void __launch_bounds__(NTH, 2)
decoder(const float* __restrict__ points,
        const float* __restrict__ b_in, const float* __restrict__ b_hid,
        const float* __restrict__ w_rgb, const float* __restrict__ b_rgb,
        const float* __restrict__ w_den, const float* __restrict__ b_den,
        const float* __restrict__ w_emb, const float* __restrict__ b_emb,
        float* __restrict__ out) {
    extern __shared__ char sm[];
    const uint32_t smb = smem_u32(sm);
    const int t = threadIdx.x, lane = t & 31, wid = t >> 5;
    const int wm = wid >> 2, wn = wid & 3;     // 2(M) x 4(N)
    const int g0 = blockIdx.x * PTS;
    const uint8_t* gw = (const uint8_t*)g_wq;

    // kick off weight chunk 0 (16KB)
    {
        const uint32_t dst = smb + SO_WBUF;
#pragma unroll
        for (int i = 0; i < 4; i++) {
            const int off = (t + i * NTH) * 16;
            CP_ASYNC16(dst + off, gw + off);
        }
        CP_COMMIT();
    }

    float* sbias = (float*)(sm + SO_SBIAS);
    float* sbs   = (float*)(sm + SO_SB);
    float* wht   = (float*)(sm + SO_WHT);
    float* rmax  = (float*)(sm + SO_RMAX);
    float* saA   = (float*)(sm + SO_SA);       // [2][64]
    float* invs  = (float*)(sm + SO_INV);
    int*   famax = (int*)(sm + SO_FAMAX);
    float* bhd   = (float*)(sm + SO_BHD);

    for (int i = t; i < 2560; i += NTH) {
        sbias[i] = (i < 256) ? b_in[i] : b_hid[i - 256];
        sbs[i] = g_sb[i];
    }
    for (int i = t; i < 256; i += NTH) {
        wht[i * 8 + 0] = w_rgb[i];        wht[i * 8 + 1] = w_rgb[256 + i];
        wht[i * 8 + 2] = w_rgb[512 + i];  wht[i * 8 + 3] = w_den[i];
        wht[i * 8 + 4] = w_emb[i];        wht[i * 8 + 5] = w_emb[256 + i];
        wht[i * 8 + 6] = w_emb[512 + i];  wht[i * 8 + 7] = 0.0f;
    }
    if (t < 64) famax[t] = 0;
    if (t < 3) bhd[t] = b_rgb[t];
    else if (t == 3) bhd[3] = b_den[0];
    else if (t < 7) bhd[t] = b_emb[t - 4];
    else if (t == 7) bhd[7] = 0.0f;
    __syncthreads();

    // ---- sampling phase A: compute feats (kept in regs), per-point |max| ----
    float frx[24], fry[24];
#pragma unroll
    for (int i = 0; i < 24; i++) {
        const int task = wid + i * 8;
        const int p = task / 3, pl = task - p * 3;
        const int g = g0 + p, b = g / NN;
        const float px = points[(size_t)g * 3 + 0];
        const float py = points[(size_t)g * 3 + 1];
        const float pz = points[(size_t)g * 3 + 2];
        float gx, gy;
        if (pl == 0)      { gx = px; gy = py; }
        else if (pl == 1) { gx = px; gy = pz; }
        else              { gx = py; gy = pz; }
        const float ix = (gx + 1.0f) * 0.5f * (float)(WW - 1);
        const float iy = (gy + 1.0f) * 0.5f * (float)(HH - 1);
        const float x0f = floorf(ix), y0f = floorf(iy);
        const float wx = ix - x0f, wy = iy - y0f;
        const int x0 = min(max((int)x0f, 0), WW - 1);
        const int x1 = min(max((int)x0f + 1, 0), WW - 1);
        const int y0 = min(max((int)y0f, 0), HH - 1);
        const int y1 = min(max((int)y0f + 1, 0), HH - 1);
        const float* base = g_trip + (size_t)(b * 3 + pl) * (HH * WW) * CC;
        const float2* c00 = (const float2*)(base + ((size_t)y0 * WW + x0) * CC);
        const float2* c01 = (const float2*)(base + ((size_t)y0 * WW + x1) * CC);
        const float2* c10 = (const float2*)(base + ((size_t)y1 * WW + x0) * CC);
        const float2* c11 = (const float2*)(base + ((size_t)y1 * WW + x1) * CC);
        const float w00 = (1.0f - wx) * (1.0f - wy), w01 = wx * (1.0f - wy);
        const float w10 = (1.0f - wx) * wy,          w11 = wx * wy;
        const float2 v00 = c00[lane], v01 = c01[lane];
        const float2 v10 = c10[lane], v11 = c11[lane];
        const float rx = v00.x * w00 + v01.x * w01 + v10.x * w10 + v11.x * w11;
        const float ry = v00.y * w00 + v01.y * w01 + v10.y * w10 + v11.y * w11;
        frx[i] = rx; fry[i] = ry;
        float am = fmaxf(fabsf(rx), fabsf(ry));
#pragma unroll
        for (int off = 16; off; off >>= 1) am = fmaxf(am, __shfl_xor_sync(0xFFFFFFFFu, am, off));
        if (lane == 0) atomicMax(&famax[p], __float_as_int(am));
    }
    __syncthreads();
    if (t < 64) {
        const float m = __int_as_float(famax[t]);
        saA[t] = m * (1.0f / 16256.0f);                 // sa[0][t]
        invs[t] = 16256.0f / fmaxf(m, 1e-20f);
    }
    __syncthreads();

    // ---- sampling phase B: digitize feats into A planes ---------------------
#pragma unroll
    for (int i = 0; i < 24; i++) {
        const int task = wid + i * 8;
        const int p = task / 3, pl = task - p * 3;
        const float inv = invs[p];
        const float qx = frx[i] * inv, qy = fry[i] * inv;
        const float d1xf = rintf(qx * 0.0078125f), d1yf = rintf(qy * 0.0078125f);
        const int d0x = __float2int_rn(qx - 128.0f * d1xf);
        const int d0y = __float2int_rn(qy - 128.0f * d1yf);
        const int d1x = (int)d1xf, d1y = (int)d1yf;
        const int col0 = pl * 64 + 2 * lane;
        const uint32_t u = (uint32_t)(col0 >> 4);
        const uint32_t base = (uint32_t)p * 256 + ((u ^ (p & 7)) << 4) + (col0 & 15);
        *(uint16_t*)(sm + SO_A1 + base) = (uint16_t)(((d1y & 0xFF) << 8) | (d1x & 0xFF));
        *(uint16_t*)(sm + SO_A0 + base) = (uint16_t)(((d0y & 0xFF) << 8) | (d0x & 0xFF));
    }
    __syncthreads();

    // ---- 10 layers ----------------------------------------------------------
    int gc = 0;
    for (int L = 0; L < 10; L++) {
        const int nch = (L == 0) ? 6 : 8;
        int acc1[2][8][4], accm[2][8][4];
#pragma unroll
        for (int mi = 0; mi < 2; mi++)
#pragma unroll
            for (int ni = 0; ni < 8; ni++)
#pragma unroll
                for (int j = 0; j < 4; j++) { acc1[mi][ni][j] = 0; accm[mi][ni][j] = 0; }

        for (int c = 0; c < nch; c++) {
            CP_WAIT0();
            __syncthreads();
            if (gc + 1 < NCHUNK_TOT) {
                const uint32_t dst = smb + SO_WBUF + ((gc + 1) & 1) * 16384;
                const uint8_t* src = gw + (size_t)(gc + 1) * 16384;
#pragma unroll
                for (int i = 0; i < 4; i++) {
                    const int off = (t + i * NTH) * 16;
                    CP_ASYNC16(dst + off, src + off);
                }
                CP_COMMIT();
            }
            const uint32_t wb = smb + SO_WBUF + (gc & 1) * 16384;

            // A fragments (d1, d0) for this k32
            uint32_t a1[2][4], a0[2][4];
#pragma unroll
            for (int mi = 0; mi < 2; mi++) {
                const uint32_t rA = (uint32_t)(wm * 32 + mi * 16 + (lane & 15));
                const uint32_t aoff = rA * 256
                    + ((((uint32_t)(c * 2 + (lane >> 4)) ^ (rA & 7))) << 4);
                ldsm4(a1[mi], smb + SO_A1 + aoff);
                ldsm4(a0[mi], smb + SO_A0 + aoff);
            }
            // B fragments + MMAs: 4 ldsm.x4 per digit cover 8 n-tiles
            const uint32_t tB = (uint32_t)(lane >> 3);
            const uint32_t rowB = (uint32_t)(lane & 7);
#pragma unroll
            for (int nt2 = 0; nt2 < 4; nt2++) {
                const uint32_t blk = (uint32_t)((wn * 8 + nt2 * 2 + (tB >> 1)) * 2 + (tB & 1));
                const uint32_t boff = blk * 128 + rowB * 16;
                uint32_t bh[4], bl[4];
                ldsm4(bh, wb + boff);
                ldsm4(bl, wb + 8192 + boff);
#pragma unroll
                for (int mi = 0; mi < 2; mi++) {
                    mma_s8(acc1[mi][nt2 * 2],     a1[mi], bh[0], bh[1]);
                    mma_s8(acc1[mi][nt2 * 2 + 1], a1[mi], bh[2], bh[3]);
                    mma_s8(accm[mi][nt2 * 2],     a1[mi], bl[0], bl[1]);
                    mma_s8(accm[mi][nt2 * 2 + 1], a1[mi], bl[2], bl[3]);
                    mma_s8(accm[mi][nt2 * 2],     a0[mi], bh[0], bh[1]);
                    mma_s8(accm[mi][nt2 * 2 + 1], a0[mi], bh[2], bh[3]);
                }
            }
            gc++;
        }
        __syncthreads();   // all warps done reading A planes

        const float* sbl = sbs + L * 256;
        const float* bl_ = sbias + L * 256;
        const float* sap = saA + (L & 1) * 64;

        if (L < 9) {
            // pass 1: row maxima
            float rmx[2][2] = {{0.0f, 0.0f}, {0.0f, 0.0f}};
#pragma unroll
            for (int mi = 0; mi < 2; mi++) {
                const int r1 = wm * 32 + mi * 16 + (lane >> 2);
                const float s0 = sap[r1], s1 = sap[r1 + 8];
#pragma unroll
                for (int ni = 0; ni < 8; ni++) {
                    const int c0 = wn * 64 + ni * 8 + 2 * (lane & 3);
                    const float f0 = sbl[c0], f1 = sbl[c0 + 1];
                    const float b0 = bl_[c0], b1 = bl_[c0 + 1];
                    float v0 = fmaxf(s0 * f0 * (16384.0f * (float)acc1[mi][ni][0] + 128.0f * (float)accm[mi][ni][0]) + b0, 0.0f);
                    float v1 = fmaxf(s0 * f1 * (16384.0f * (float)acc1[mi][ni][1] + 128.0f * (float)accm[mi][ni][1]) + b1, 0.0f);
                    float v2 = fmaxf(s1 * f0 * (16384.0f * (float)acc1[mi][ni][2] + 128.0f * (float)accm[mi][ni][2]) + b0, 0.0f);
                    float v3 = fmaxf(s1 * f1 * (16384.0f * (float)acc1[mi][ni][3] + 128.0f * (float)accm[mi][ni][3]) + b1, 0.0f);
                    rmx[mi][0] = fmaxf(rmx[mi][0], fmaxf(v0, v1));
                    rmx[mi][1] = fmaxf(rmx[mi][1], fmaxf(v2, v3));
                }
            }
#pragma unroll
            for (int d = 1; d <= 2; d <<= 1) {
#pragma unroll
                for (int mi = 0; mi < 2; mi++) {
                    rmx[mi][0] = fmaxf(rmx[mi][0], __shfl_xor_sync(0xFFFFFFFFu, rmx[mi][0], d));
                    rmx[mi][1] = fmaxf(rmx[mi][1], __shfl_xor_sync(0xFFFFFFFFu, rmx[mi][1], d));
                }
            }
            if ((lane & 3) == 0) {
#pragma unroll
                for (int mi = 0; mi < 2; mi++) {
                    rmax[(wm * 32 + mi * 16 + (lane >> 2)) * 4 + wn] = rmx[mi][0];
                    rmax[(wm * 32 + mi * 16 + 8 + (lane >> 2)) * 4 + wn] = rmx[mi][1];
                }
            }
            __syncthreads();
            if (t < 64) {
                const float m = fmaxf(fmaxf(rmax[t * 4], rmax[t * 4 + 1]),
                                      fmaxf(rmax[t * 4 + 2], rmax[t * 4 + 3]));
                saA[((L + 1) & 1) * 64 + t] = m * (1.0f / 16256.0f);
                invs[t] = 16256.0f / fmaxf(m, 1e-20f);
            }
            __syncthreads();
            // pass 2: digitize + store A planes
#pragma unroll
            for (int mi = 0; mi < 2; mi++) {
                const int r1 = wm * 32 + mi * 16 + (lane >> 2);
                const float s0 = sap[r1], s1 = sap[r1 + 8];
                const float i0 = invs[r1], i1 = invs[r1 + 8];
#pragma unroll
                for (int ni = 0; ni < 8; ni++) {
                    const int c0 = wn * 64 + ni * 8 + 2 * (lane & 3);
                    const float f0 = sbl[c0], f1 = sbl[c0 + 1];
                    const float b0 = bl_[c0], b1 = bl_[c0 + 1];
                    float v0 = fmaxf(s0 * f0 * (16384.0f * (float)acc1[mi][ni][0] + 128.0f * (float)accm[mi][ni][0]) + b0, 0.0f);
                    float v1 = fmaxf(s0 * f1 * (16384.0f * (float)acc1[mi][ni][1] + 128.0f * (float)accm[mi][ni][1]) + b1, 0.0f);
                    float v2 = fmaxf(s1 * f0 * (16384.0f * (float)acc1[mi][ni][2] + 128.0f * (float)accm[mi][ni][2]) + b0, 0.0f);
                    float v3 = fmaxf(s1 * f1 * (16384.0f * (float)acc1[mi][ni][3] + 128.0f * (float)accm[mi][ni][3]) + b1, 0.0f);
                    const float q0 = v0 * i0, q1 = v1 * i0, q2 = v2 * i1, q3 = v3 * i1;
                    const float e0 = rintf(q0 * 0.0078125f), e1 = rintf(q1 * 0.0078125f);
                    const float e2 = rintf(q2 * 0.0078125f), e3 = rintf(q3 * 0.0078125f);
                    const int g0i = __float2int_rn(q0 - 128.0f * e0);
                    const int g1i = __float2int_rn(q1 - 128.0f * e1);
                    const int g2i = __float2int_rn(q2 - 128.0f * e2);
                    const int g3i = __float2int_rn(q3 - 128.0f * e3);
                    const uint32_t u = (uint32_t)(c0 >> 4);
                    const uint32_t ba = (uint32_t)r1 * 256 + ((u ^ (r1 & 7)) << 4) + (c0 & 15);
                    *(uint16_t*)(sm + SO_A1 + ba) = (uint16_t)((((int)e1 & 0xFF) << 8) | ((int)e0 & 0xFF));
                    *(uint16_t*)(sm + SO_A0 + ba) = (uint16_t)(((g1i & 0xFF) << 8) | (g0i & 0xFF));
                    *(uint16_t*)(sm + SO_A1 + ba + 2048) = (uint16_t)((((int)e3 & 0xFF) << 8) | ((int)e2 & 0xFF));
                    *(uint16_t*)(sm + SO_A0 + ba + 2048) = (uint16_t)(((g3i & 0xFF) << 8) | (g2i & 0xFF));
                }
            }
        } else {
            // final layer: dequant -> f32 acts at SO_ACT [64][256]
            float* act = (float*)(sm + SO_ACT);
#pragma unroll
            for (int mi = 0; mi < 2; mi++) {
                const int r1 = wm * 32 + mi * 16 + (lane >> 2);
                const float s0 = sap[r1], s1 = sap[r1 + 8];
#pragma unroll
                for (int ni = 0; ni < 8; ni++) {
                    const int c0 = wn * 64 + ni * 8 + 2 * (lane & 3);
                    const float f0 = sbl[c0], f1 = sbl[c0 + 1];
                    const float b0 = bl_[c0], b1 = bl_[c0 + 1];
                    act[r1 * 256 + c0]           = fmaxf(s0 * f0 * (16384.0f * (float)acc1[mi][ni][0] + 128.0f * (float)accm[mi][ni][0]) + b0, 0.0f);
                    act[r1 * 256 + c0 + 1]       = fmaxf(s0 * f1 * (16384.0f * (float)acc1[mi][ni][1] + 128.0f * (float)accm[mi][ni][1]) + b1, 0.0f);
                    act[(r1 + 8) * 256 + c0]     = fmaxf(s1 * f0 * (16384.0f * (float)acc1[mi][ni][2] + 128.0f * (float)accm[mi][ni][2]) + b0, 0.0f);
                    act[(r1 + 8) * 256 + c0 + 1] = fmaxf(s1 * f1 * (16384.0f * (float)acc1[mi][ni][3] + 128.0f * (float)accm[mi][ni][3]) + b1, 0.0f);
                }
            }
        }
        __syncthreads();
    }

    // ---- heads --------------------------------------------------------------
    const float* hf = (const float*)(sm + SO_ACT);
    for (int task = wid; task < PTS * 7; task += 8) {
        const int p = task & 63;
        const int j = task >> 6;
        const float4* hp = (const float4*)(hf + p * 256);
        float s = 0.0f;
#pragma unroll
        for (int ii = 0; ii < 2; ii++) {
            const float4 hv = hp[lane + ii * 32];
            const int c0 = (lane + ii * 32) * 4;
            s += hv.x * wht[(c0 + 0) * 8 + j] + hv.y * wht[(c0 + 1) * 8 + j]
               + hv.z * wht[(c0 + 2) * 8 + j] + hv.w * wht[(c0 + 3) * 8 + j];
        }
#pragma unroll
        for (int off = 16; off; off >>= 1) s += __shfl_xor_sync(0xFFFFFFFFu, s, off);
        if (lane == 0) {
            s += bhd[j];
            const int g = g0 + p;
            if (j < 3)
                out[(size_t)g * 3 + j] = 1.0f / (1.0f + expf(-s));
            else if (j == 3)
                out[(size_t)BB * NN * 3 + g] = s;
            else
                out[(size_t)BB * NN * 4 + (size_t)g * 3 + (j - 4)] = s;
        }
    }
}

// ---------------------------------------------------------------------------
extern "C" void kernel_launch(void* const* d_in, const int* in_sizes, int n_in,
                              void* d_out, int out_size) {
    const float* triplane = (const float*)d_in[0];
    const float* points   = (const float*)d_in[1];
    const float* w_in     = (const float*)d_in[2];
    const float* b_in     = (const float*)d_in[3];
    const float* w_hid    = (const float*)d_in[4];
    const float* b_hid    = (const float*)d_in[5];
    const float* w_rgb    = (const float*)d_in[6];
    const float* b_rgb    = (const float*)d_in[7];
    const float* w_den    = (const float*)d_in[8];
    const float* b_den    = (const float*)d_in[9];
    const float* w_emb    = (const float*)d_in[10];
    const float* b_emb    = (const float*)d_in[11];
    float* out = (float*)d_out;

    transpose_trip<<<dim3((HH * WW) / 32, BB * 3), 256>>>(triplane);
    prep_weights<<<320, 256>>>(w_in, w_hid);

    cudaFuncSetAttribute(decoder, cudaFuncAttributeMaxDynamicSharedMemorySize, SMEM_TOT);
    decoder<<<(BB * NN) / PTS, NTH, SMEM_TOT>>>(
        points, b_in, b_hid, w_rgb, b_rgb, w_den, b_den, w_emb, b_emb, out);
}

// round 10
// speedup vs baseline: 1.1259x; 1.1259x over previous
#include <cuda_runtime.h>
#include <math.h>
#include <stdint.h>

// ---------------------------------------------------------------------------
// TriplaneDecoder via int8 double-digit mma.sync (m16n8k32.s8) — compute_100.
// x = s*(d1*128 + d0). D = sa*sb*(16384*S11 + 128*S1m), S1m = d1a.d0b+d0a.d1b.
// R9b: chunk = 128 k-rows (64KB, double-buffered) -> barriers 78 -> 20;
// L0 zero-padded to K=256; prefetch spread across k-steps.
// FIX vs R9: A-plane zero-init was overrunning 16KB into SO_WBUF (raced with
// the chunk-0 cp.async, zeroing half of L0's d1 weights). Single 32KB loop now.
// CTA = 64 points, 8 warps 2(M)x4(N), warp tile 32x64. 1 CTA/SM (190KB smem).
// ---------------------------------------------------------------------------

#define BB 4
#define NN 100000
#define CC 64
#define HH 256
#define WW 256
#define PTS 64
#define NTH 256
#define NCHUNK_TOT 20     // 10 layers x 2 chunks x 64KB

// smem byte offsets
#define SO_A1    0        // A d1 plane: 64 x 256 s8 (16KB)
#define SO_A0    16384    // A d0 plane (16KB)
#define SO_WBUF  32768    // 2 x 64KB weight chunk buffers (d1 32KB | d0 32KB)
#define SO_ACT   0        // overlay (final f32 acts 64x256 = 64KB)
#define SO_SBIAS 163840   // biases 10*256 f32
#define SO_SB    174080   // weight col scales 10*256 f32
#define SO_WHT   184320   // head weights [256][8] f32
#define SO_RMAX  192512   // rowmax partials [64][4] f32
#define SO_SA    193536   // A row scales, ping-pong [2][64] f32
#define SO_INV   194048   // inv scale [64] f32
#define SO_FAMAX 194304   // feat |max| bits [64] u32
#define SO_BHD   194560   // head biases [8]
#define SMEM_TOT 194592

__device__ float g_trip[(size_t)BB * 3 * HH * WW * CC];
__device__ uint4 g_wq[1310720 / 16];       // 20 x 64KB chunks (zero-init pads L0)
__device__ float g_sb[10 * 256];           // per-output weight scales

// ---- PTX helpers -----------------------------------------------------------
__device__ __forceinline__ uint32_t smem_u32(const void* p) {
    uint32_t a;
    asm("{ .reg .u64 t; cvta.to.shared.u64 t, %1; cvt.u32.u64 %0, t; }" : "=r"(a) : "l"(p));
    return a;
}
__device__ __forceinline__ void ldsm4(uint32_t* r, uint32_t a) {
    asm volatile("ldmatrix.sync.aligned.m8n8.x4.shared.b16 {%0,%1,%2,%3}, [%4];"
                 : "=r"(r[0]), "=r"(r[1]), "=r"(r[2]), "=r"(r[3]) : "r"(a));
}
__device__ __forceinline__ void mma_s8(int* c, const uint32_t* a, uint32_t b0, uint32_t b1) {
    asm volatile("mma.sync.aligned.m16n8k32.row.col.s32.s8.s8.s32 "
                 "{%0,%1,%2,%3}, {%4,%5,%6,%7}, {%8,%9}, {%0,%1,%2,%3};"
                 : "+r"(c[0]), "+r"(c[1]), "+r"(c[2]), "+r"(c[3])
                 : "r"(a[0]), "r"(a[1]), "r"(a[2]), "r"(a[3]), "r"(b0), "r"(b1));
}
#define CP_ASYNC16(dst, src) \
    asm volatile("cp.async.cg.shared.global [%0], [%1], 16;" :: "r"(dst), "l"(src))
#define CP_COMMIT() asm volatile("cp.async.commit_group;")
#define CP_WAIT0()  asm volatile("cp.async.wait_group 0;")

// ---------------- prolog 1: triplane [pl][C][HW] -> [pl][HW][C] -------------
__global__ void transpose_trip(const float* __restrict__ in) {
    __shared__ float s[64][33];
    const int plane = blockIdx.y;
    const int hw0 = blockIdx.x * 32;
    const float* ip = in + (size_t)plane * CC * HH * WW;
    float* op = g_trip + (size_t)plane * HH * WW * CC;
    const int t = threadIdx.x, l32 = t & 31, grp = t >> 5;
#pragma unroll
    for (int i = 0; i < 8; i++) {
        int c = grp + i * 8;
        s[c][l32] = ip[(size_t)c * (HH * WW) + hw0 + l32];
    }
    __syncthreads();
    const int c2 = t & 63, r0 = t >> 6;
#pragma unroll
    for (int j = 0; j < 8; j++) {
        int r = r0 + j * 4;
        op[(size_t)(hw0 + r) * CC + c2] = s[c2][r];
    }
}

// ---------------- prolog 2: weight quantization -----------------------------
// one warp per (L, n). gmem chunk = L*2 + (k>>7), 64KB (d1 32KB | d0 32KB).
// within plane: blk = (n>>3)*8 + ((k>>4)&7); off = blk*128 + (n&7)*16 + (k&15).
// L0 region for k in [192,256) stays zero (g_wq zero-init).
__global__ void prep_weights(const float* __restrict__ w_in,
                             const float* __restrict__ w_hid) {
    const int lane = threadIdx.x & 31;
    const int id = blockIdx.x * 8 + (threadIdx.x >> 5);
    if (id >= 2560) return;
    const int L = id >> 8, n = id & 255;
    const int K = (L == 0) ? 192 : 256;
    float vals[8];
    float m = 0.0f;
#pragma unroll
    for (int j = 0; j < 8; j++) {
        const int k = lane + j * 32;
        float v = 0.0f;
        if (k < K)
            v = (L == 0) ? w_in[n * 192 + k] : w_hid[(size_t)(L - 1) * 65536 + n * 256 + k];
        vals[j] = v;
        m = fmaxf(m, fabsf(v));
    }
#pragma unroll
    for (int off = 16; off; off >>= 1) m = fmaxf(m, __shfl_xor_sync(0xFFFFFFFFu, m, off));
    const float inv = 16256.0f / fmaxf(m, 1e-30f);
    int8_t* gw = (int8_t*)g_wq;
#pragma unroll
    for (int j = 0; j < 8; j++) {
        const int k = lane + j * 32;
        if (k >= K) break;
        const float q = vals[j] * inv;
        const float d1f = rintf(q * 0.0078125f);
        const int d0 = __float2int_rn(q - 128.0f * d1f);
        const int d1 = (int)d1f;
        const size_t a = (size_t)(L * 2 + (k >> 7)) * 65536
                       + (size_t)(((n >> 3) * 8 + ((k >> 4) & 7)) * 128 + (n & 7) * 16 + (k & 15));
        gw[a] = (int8_t)d1;
        gw[a + 32768] = (int8_t)d0;
    }
    if (lane == 0) g_sb[id] = m * (1.0f / 16256.0f);
}

// ---------------- main fused decoder ----------------------------------------
__global__ void __launch_bounds__(NTH, 1)
decoder(const float* __restrict__ points,
        const float* __restrict__ b_in, const float* __restrict__ b_hid,
        const float* __restrict__ w_rgb, const float* __restrict__ b_rgb,
        const float* __restrict__ w_den, const float* __restrict__ b_den,
        const float* __restrict__ w_emb, const float* __restrict__ b_emb,
        float* __restrict__ out) {
    extern __shared__ char sm[];
    const uint32_t smb = smem_u32(sm);
    const int t = threadIdx.x, lane = t & 31, wid = t >> 5;
    const int wm = wid >> 2, wn = wid & 3;     // 2(M) x 4(N)
    const int g0 = blockIdx.x * PTS;
    const uint8_t* gw = (const uint8_t*)g_wq;

    // kick off weight chunk 0 (64KB; overlaps sampling)
    {
        const uint32_t dst = smb + SO_WBUF;
#pragma unroll
        for (int i = 0; i < 16; i++) {
            const int off = (t + i * NTH) * 16;
            CP_ASYNC16(dst + off, gw + off);
        }
        CP_COMMIT();
    }

    float* sbias = (float*)(sm + SO_SBIAS);
    float* sbs   = (float*)(sm + SO_SB);
    float* wht   = (float*)(sm + SO_WHT);
    float* rmax  = (float*)(sm + SO_RMAX);
    float* saA   = (float*)(sm + SO_SA);       // [2][64]
    float* invs  = (float*)(sm + SO_INV);
    int*   famax = (int*)(sm + SO_FAMAX);
    float* bhd   = (float*)(sm + SO_BHD);

    for (int i = t; i < 2560; i += NTH) {
        sbias[i] = (i < 256) ? b_in[i] : b_hid[i - 256];
        sbs[i] = g_sb[i];
    }
    for (int i = t; i < 256; i += NTH) {
        wht[i * 8 + 0] = w_rgb[i];        wht[i * 8 + 1] = w_rgb[256 + i];
        wht[i * 8 + 2] = w_rgb[512 + i];  wht[i * 8 + 3] = w_den[i];
        wht[i * 8 + 4] = w_emb[i];        wht[i * 8 + 5] = w_emb[256 + i];
        wht[i * 8 + 6] = w_emb[512 + i];  wht[i * 8 + 7] = 0.0f;
    }
    // zero BOTH A planes with ONE 32KB loop (A1 16KB + A0 16KB, exact;
    // must NOT touch SO_WBUF — chunk-0 cp.async is in flight there)
    {
        uint4 z = {0u, 0u, 0u, 0u};
        uint4* ap = (uint4*)(sm + SO_A1);
#pragma unroll
        for (int i = 0; i < 8; i++) ap[t + i * NTH] = z;   // 2048 uint4 = 32KB
    }
    if (t < 64) famax[t] = 0;
    if (t < 3) bhd[t] = b_rgb[t];
    else if (t == 3) bhd[3] = b_den[0];
    else if (t < 7) bhd[t] = b_emb[t - 4];
    else if (t == 7) bhd[7] = 0.0f;
    __syncthreads();

    // ---- sampling phase A: compute feats (kept in regs), per-point |max| ----
    float frx[24], fry[24];
#pragma unroll
    for (int i = 0; i < 24; i++) {
        const int task = wid + i * 8;
        const int p = task / 3, pl = task - p * 3;
        const int g = g0 + p, b = g / NN;
        const float px = points[(size_t)g * 3 + 0];
        const float py = points[(size_t)g * 3 + 1];
        const float pz = points[(size_t)g * 3 + 2];
        float gx, gy;
        if (pl == 0)      { gx = px; gy = py; }
        else if (pl == 1) { gx = px; gy = pz; }
        else              { gx = py; gy = pz; }
        const float ix = (gx + 1.0f) * 0.5f * (float)(WW - 1);
        const float iy = (gy + 1.0f) * 0.5f * (float)(HH - 1);
        const float x0f = floorf(ix), y0f = floorf(iy);
        const float wx = ix - x0f, wy = iy - y0f;
        const int x0 = min(max((int)x0f, 0), WW - 1);
        const int x1 = min(max((int)x0f + 1, 0), WW - 1);
        const int y0 = min(max((int)y0f, 0), HH - 1);
        const int y1 = min(max((int)y0f + 1, 0), HH - 1);
        const float* base = g_trip + (size_t)(b * 3 + pl) * (HH * WW) * CC;
        const float2* c00 = (const float2*)(base + ((size_t)y0 * WW + x0) * CC);
        const float2* c01 = (const float2*)(base + ((size_t)y0 * WW + x1) * CC);
        const float2* c10 = (const float2*)(base + ((size_t)y1 * WW + x0) * CC);
        const float2* c11 = (const float2*)(base + ((size_t)y1 * WW + x1) * CC);
        const float w00 = (1.0f - wx) * (1.0f - wy), w01 = wx * (1.0f - wy);
        const float w10 = (1.0f - wx) * wy,          w11 = wx * wy;
        const float2 v00 = c00[lane], v01 = c01[lane];
        const float2 v10 = c10[lane], v11 = c11[lane];
        const float rx = v00.x * w00 + v01.x * w01 + v10.x * w10 + v11.x * w11;
        const float ry = v00.y * w00 + v01.y * w01 + v10.y * w10 + v11.y * w11;
        frx[i] = rx; fry[i] = ry;
        float am = fmaxf(fabsf(rx), fabsf(ry));
#pragma unroll
        for (int off = 16; off; off >>= 1) am = fmaxf(am, __shfl_xor_sync(0xFFFFFFFFu, am, off));
        if (lane == 0) atomicMax(&famax[p], __float_as_int(am));
    }
    __syncthreads();
    if (t < 64) {
        const float m = __int_as_float(famax[t]);
        saA[t] = m * (1.0f / 16256.0f);                 // sa[0][t]
        invs[t] = 16256.0f / fmaxf(m, 1e-20f);
    }
    __syncthreads();

    // ---- sampling phase B: digitize feats into A planes ---------------------
#pragma unroll
    for (int i = 0; i < 24; i++) {
        const int task = wid + i * 8;
        const int p = task / 3, pl = task - p * 3;
        const float inv = invs[p];
        const float qx = frx[i] * inv, qy = fry[i] * inv;
        const float d1xf = rintf(qx * 0.0078125f), d1yf = rintf(qy * 0.0078125f);
        const int d0x = __float2int_rn(qx - 128.0f * d1xf);
        const int d0y = __float2int_rn(qy - 128.0f * d1yf);
        const int d1x = (int)d1xf, d1y = (int)d1yf;
        const int col0 = pl * 64 + 2 * lane;
        const uint32_t u = (uint32_t)(col0 >> 4);
        const uint32_t base = (uint32_t)p * 256 + ((u ^ (p & 7)) << 4) + (col0 & 15);
        *(uint16_t*)(sm + SO_A1 + base) = (uint16_t)(((d1y & 0xFF) << 8) | (d1x & 0xFF));
        *(uint16_t*)(sm + SO_A0 + base) = (uint16_t)(((d0y & 0xFF) << 8) | (d0x & 0xFF));
    }
    __syncthreads();

    // ---- 10 layers ----------------------------------------------------------
    int gc = 0;
    for (int L = 0; L < 10; L++) {
        int acc1[2][8][4], accm[2][8][4];
#pragma unroll
        for (int mi = 0; mi < 2; mi++)
#pragma unroll
            for (int ni = 0; ni < 8; ni++)
#pragma unroll
                for (int j = 0; j < 4; j++) { acc1[mi][ni][j] = 0; accm[mi][ni][j] = 0; }

        for (int ch = 0; ch < 2; ch++) {
            CP_WAIT0();
            __syncthreads();
            const uint32_t wb = smb + SO_WBUF + (gc & 1) * 65536;
            const int nxt = gc + 1;
            const uint32_t pdst = smb + SO_WBUF + (nxt & 1) * 65536;
            const uint8_t* psrc = gw + (size_t)nxt * 65536;
            const uint32_t tB = (uint32_t)(lane >> 3);
            const uint32_t rowB = (uint32_t)(lane & 7);

#pragma unroll
            for (int ks = 0; ks < 4; ks++) {
                if (nxt < NCHUNK_TOT) {       // spread prefetch: 4 cp.async / ks
#pragma unroll
                    for (int i = 0; i < 4; i++) {
                        const int off = (t + (ks * 4 + i) * NTH) * 16;
                        CP_ASYNC16(pdst + off, psrc + off);
                    }
                }
                // A fragments (d1, d0) for this k32
                uint32_t a1[2][4], a0[2][4];
#pragma unroll
                for (int mi = 0; mi < 2; mi++) {
                    const uint32_t rA = (uint32_t)(wm * 32 + mi * 16 + (lane & 15));
                    const uint32_t uu = (uint32_t)(ch * 8 + ks * 2 + (lane >> 4));
                    const uint32_t aoff = rA * 256 + ((uu ^ (rA & 7)) << 4);
                    ldsm4(a1[mi], smb + SO_A1 + aoff);
                    ldsm4(a0[mi], smb + SO_A0 + aoff);
                }
                // B fragments + MMAs
#pragma unroll
                for (int nt2 = 0; nt2 < 4; nt2++) {
                    const uint32_t blk = (uint32_t)((wn * 8 + nt2 * 2 + (tB >> 1)) * 8
                                                    + ks * 2 + (tB & 1));
                    const uint32_t boff = blk * 128 + rowB * 16;
                    uint32_t bh[4], bl[4];
                    ldsm4(bh, wb + boff);
                    ldsm4(bl, wb + 32768 + boff);
#pragma unroll
                    for (int mi = 0; mi < 2; mi++) {
                        mma_s8(acc1[mi][nt2 * 2],     a1[mi], bh[0], bh[1]);
                        mma_s8(acc1[mi][nt2 * 2 + 1], a1[mi], bh[2], bh[3]);
                        mma_s8(accm[mi][nt2 * 2],     a1[mi], bl[0], bl[1]);
                        mma_s8(accm[mi][nt2 * 2 + 1], a1[mi], bl[2], bl[3]);
                        mma_s8(accm[mi][nt2 * 2],     a0[mi], bh[0], bh[1]);
                        mma_s8(accm[mi][nt2 * 2 + 1], a0[mi], bh[2], bh[3]);
                    }
                }
            }
            if (nxt < NCHUNK_TOT) CP_COMMIT();
            gc++;
        }
        __syncthreads();   // all warps done reading A planes

        const float* sbl = sbs + L * 256;
        const float* bl_ = sbias + L * 256;
        const float* sap = saA + (L & 1) * 64;

        if (L < 9) {
            // pass 1: row maxima
            float rmx[2][2] = {{0.0f, 0.0f}, {0.0f, 0.0f}};
#pragma unroll
            for (int mi = 0; mi < 2; mi++) {
                const int r1 = wm * 32 + mi * 16 + (lane >> 2);
                const float s0 = sap[r1], s1 = sap[r1 + 8];
#pragma unroll
                for (int ni = 0; ni < 8; ni++) {
                    const int c0 = wn * 64 + ni * 8 + 2 * (lane & 3);
                    const float f0 = sbl[c0], f1 = sbl[c0 + 1];
                    const float b0 = bl_[c0], b1 = bl_[c0 + 1];
                    float v0 = fmaxf(s0 * f0 * (16384.0f * (float)acc1[mi][ni][0] + 128.0f * (float)accm[mi][ni][0]) + b0, 0.0f);
                    float v1 = fmaxf(s0 * f1 * (16384.0f * (float)acc1[mi][ni][1] + 128.0f * (float)accm[mi][ni][1]) + b1, 0.0f);
                    float v2 = fmaxf(s1 * f0 * (16384.0f * (float)acc1[mi][ni][2] + 128.0f * (float)accm[mi][ni][2]) + b0, 0.0f);
                    float v3 = fmaxf(s1 * f1 * (16384.0f * (float)acc1[mi][ni][3] + 128.0f * (float)accm[mi][ni][3]) + b1, 0.0f);
                    rmx[mi][0] = fmaxf(rmx[mi][0], fmaxf(v0, v1));
                    rmx[mi][1] = fmaxf(rmx[mi][1], fmaxf(v2, v3));
                }
            }
#pragma unroll
            for (int d = 1; d <= 2; d <<= 1) {
#pragma unroll
                for (int mi = 0; mi < 2; mi++) {
                    rmx[mi][0] = fmaxf(rmx[mi][0], __shfl_xor_sync(0xFFFFFFFFu, rmx[mi][0], d));
                    rmx[mi][1] = fmaxf(rmx[mi][1], __shfl_xor_sync(0xFFFFFFFFu, rmx[mi][1], d));
                }
            }
            if ((lane & 3) == 0) {
#pragma unroll
                for (int mi = 0; mi < 2; mi++) {
                    rmax[(wm * 32 + mi * 16 + (lane >> 2)) * 4 + wn] = rmx[mi][0];
                    rmax[(wm * 32 + mi * 16 + 8 + (lane >> 2)) * 4 + wn] = rmx[mi][1];
                }
            }
            __syncthreads();
            if (t < 64) {
                const float m = fmaxf(fmaxf(rmax[t * 4], rmax[t * 4 + 1]),
                                      fmaxf(rmax[t * 4 + 2], rmax[t * 4 + 3]));
                saA[((L + 1) & 1) * 64 + t] = m * (1.0f / 16256.0f);
                invs[t] = 16256.0f / fmaxf(m, 1e-20f);
            }
            __syncthreads();
            // pass 2: digitize + store A planes
#pragma unroll
            for (int mi = 0; mi < 2; mi++) {
                const int r1 = wm * 32 + mi * 16 + (lane >> 2);
                const float s0 = sap[r1], s1 = sap[r1 + 8];
                const float i0 = invs[r1], i1 = invs[r1 + 8];
#pragma unroll
                for (int ni = 0; ni < 8; ni++) {
                    const int c0 = wn * 64 + ni * 8 + 2 * (lane & 3);
                    const float f0 = sbl[c0], f1 = sbl[c0 + 1];
                    const float b0 = bl_[c0], b1 = bl_[c0 + 1];
                    float v0 = fmaxf(s0 * f0 * (16384.0f * (float)acc1[mi][ni][0] + 128.0f * (float)accm[mi][ni][0]) + b0, 0.0f);
                    float v1 = fmaxf(s0 * f1 * (16384.0f * (float)acc1[mi][ni][1] + 128.0f * (float)accm[mi][ni][1]) + b1, 0.0f);
                    float v2 = fmaxf(s1 * f0 * (16384.0f * (float)acc1[mi][ni][2] + 128.0f * (float)accm[mi][ni][2]) + b0, 0.0f);
                    float v3 = fmaxf(s1 * f1 * (16384.0f * (float)acc1[mi][ni][3] + 128.0f * (float)accm[mi][ni][3]) + b1, 0.0f);
                    const float q0 = v0 * i0, q1 = v1 * i0, q2 = v2 * i1, q3 = v3 * i1;
                    const float e0 = rintf(q0 * 0.0078125f), e1 = rintf(q1 * 0.0078125f);
                    const float e2 = rintf(q2 * 0.0078125f), e3 = rintf(q3 * 0.0078125f);
                    const int g0i = __float2int_rn(q0 - 128.0f * e0);
                    const int g1i = __float2int_rn(q1 - 128.0f * e1);
                    const int g2i = __float2int_rn(q2 - 128.0f * e2);
                    const int g3i = __float2int_rn(q3 - 128.0f * e3);
                    const uint32_t u = (uint32_t)(c0 >> 4);
                    const uint32_t ba = (uint32_t)r1 * 256 + ((u ^ (r1 & 7)) << 4) + (c0 & 15);
                    *(uint16_t*)(sm + SO_A1 + ba) = (uint16_t)((((int)e1 & 0xFF) << 8) | ((int)e0 & 0xFF));
                    *(uint16_t*)(sm + SO_A0 + ba) = (uint16_t)(((g1i & 0xFF) << 8) | (g0i & 0xFF));
                    *(uint16_t*)(sm + SO_A1 + ba + 2048) = (uint16_t)((((int)e3 & 0xFF) << 8) | ((int)e2 & 0xFF));
                    *(uint16_t*)(sm + SO_A0 + ba + 2048) = (uint16_t)(((g3i & 0xFF) << 8) | (g2i & 0xFF));
                }
            }
        } else {
            // final layer: dequant -> f32 acts at SO_ACT [64][256]
            float* act = (float*)(sm + SO_ACT);
#pragma unroll
            for (int mi = 0; mi < 2; mi++) {
                const int r1 = wm * 32 + mi * 16 + (lane >> 2);
                const float s0 = sap[r1], s1 = sap[r1 + 8];
#pragma unroll
                for (int ni = 0; ni < 8; ni++) {
                    const int c0 = wn * 64 + ni * 8 + 2 * (lane & 3);
                    const float f0 = sbl[c0], f1 = sbl[c0 + 1];
                    const float b0 = bl_[c0], b1 = bl_[c0 + 1];
                    act[r1 * 256 + c0]           = fmaxf(s0 * f0 * (16384.0f * (float)acc1[mi][ni][0] + 128.0f * (float)accm[mi][ni][0]) + b0, 0.0f);
                    act[r1 * 256 + c0 + 1]       = fmaxf(s0 * f1 * (16384.0f * (float)acc1[mi][ni][1] + 128.0f * (float)accm[mi][ni][1]) + b1, 0.0f);
                    act[(r1 + 8) * 256 + c0]     = fmaxf(s1 * f0 * (16384.0f * (float)acc1[mi][ni][2] + 128.0f * (float)accm[mi][ni][2]) + b0, 0.0f);
                    act[(r1 + 8) * 256 + c0 + 1] = fmaxf(s1 * f1 * (16384.0f * (float)acc1[mi][ni][3] + 128.0f * (float)accm[mi][ni][3]) + b1, 0.0f);
                }
            }
        }
        __syncthreads();
    }

    // ---- heads --------------------------------------------------------------
    const float* hf = (const float*)(sm + SO_ACT);
    for (int task = wid; task < PTS * 7; task += 8) {
        const int p = task & 63;
        const int j = task >> 6;
        const float4* hp = (const float4*)(hf + p * 256);
        float s = 0.0f;
#pragma unroll
        for (int ii = 0; ii < 2; ii++) {
            const float4 hv = hp[lane + ii * 32];
            const int c0 = (lane + ii * 32) * 4;
            s += hv.x * wht[(c0 + 0) * 8 + j] + hv.y * wht[(c0 + 1) * 8 + j]
               + hv.z * wht[(c0 + 2) * 8 + j] + hv.w * wht[(c0 + 3) * 8 + j];
        }
#pragma unroll
        for (int off = 16; off; off >>= 1) s += __shfl_xor_sync(0xFFFFFFFFu, s, off);
        if (lane == 0) {
            s += bhd[j];
            const int g = g0 + p;
            if (j < 3)
                out[(size_t)g * 3 + j] = 1.0f / (1.0f + expf(-s));
            else if (j == 3)
                out[(size_t)BB * NN * 3 + g] = s;
            else
                out[(size_t)BB * NN * 4 + (size_t)g * 3 + (j - 4)] = s;
        }
    }
}

// ---------------------------------------------------------------------------
extern "C" void kernel_launch(void* const* d_in, const int* in_sizes, int n_in,
                              void* d_out, int out_size) {
    const float* triplane = (const float*)d_in[0];
    const float* points   = (const float*)d_in[1];
    const float* w_in     = (const float*)d_in[2];
    const float* b_in     = (const float*)d_in[3];
    const float* w_hid    = (const float*)d_in[4];
    const float* b_hid    = (const float*)d_in[5];
    const float* w_rgb    = (const float*)d_in[6];
    const float* b_rgb    = (const float*)d_in[7];
    const float* w_den    = (const float*)d_in[8];
    const float* b_den    = (const float*)d_in[9];
    const float* w_emb    = (const float*)d_in[10];
    const float* b_emb    = (const float*)d_in[11];
    float* out = (float*)d_out;

    transpose_trip<<<dim3((HH * WW) / 32, BB * 3), 256>>>(triplane);
    prep_weights<<<320, 256>>>(w_in, w_hid);

    cudaFuncSetAttribute(decoder, cudaFuncAttributeMaxDynamicSharedMemorySize, SMEM_TOT);
    decoder<<<(BB * NN) / PTS, NTH, SMEM_TOT>>>(
        points, b_in, b_hid, w_rgb, b_rgb, w_den, b_den, w_emb, b_emb, out);
}

// round 11
// speedup vs baseline: 1.2231x; 1.0863x over previous
#include <cuda_runtime.h>
#include <math.h>
#include <stdint.h>

// ---------------------------------------------------------------------------
// TriplaneDecoder via int8 double-digit mma.sync (m16n8k32.s8) — compute_100.
// x = s*(d1*128 + d0). D = sa*sb*(16384*S11 + 128*S1m), S1m = d1a.d0b+d0a.d1b.
// R11: 16 warps (4Mx4N, warp tile 16x64) -> 4 warps/SMSP latency cover;
// epilogue pass1 caches dequantized v in dead acc regs (no recompute);
// one sync/layer removed (row scales computed locally from rmax partials).
// Chunks: 64KB double-buffered (20 barriers total), L0 zero-padded to K=256.
// ---------------------------------------------------------------------------

#define BB 4
#define NN 100000
#define CC 64
#define HH 256
#define WW 256
#define PTS 64
#define NTH 512
#define NCHUNK_TOT 20     // 10 layers x 2 chunks x 64KB

// smem byte offsets
#define SO_A1    0        // A d1 plane: 64 x 256 s8 (16KB)
#define SO_A0    16384    // A d0 plane (16KB)
#define SO_WBUF  32768    // 2 x 64KB weight chunk buffers (d1 32KB | d0 32KB)
#define SO_ACT   0        // overlay (final f32 acts 64x256 = 64KB)
#define SO_SBIAS 163840   // biases 10*256 f32
#define SO_SB    174080   // weight col scales 10*256 f32
#define SO_WHT   184320   // head weights [256][8] f32
#define SO_RMAX  192512   // rowmax partials [64][4] f32
#define SO_SA    193536   // A row scales, ping-pong [2][64] f32
#define SO_INV   194048   // inv scale [64] f32 (sampling only)
#define SO_FAMAX 194304   // feat |max| bits [64] u32
#define SO_BHD   194560   // head biases [8]
#define SMEM_TOT 194592

__device__ float g_trip[(size_t)BB * 3 * HH * WW * CC];
__device__ uint4 g_wq[1310720 / 16];       // 20 x 64KB chunks (zero-init pads L0)
__device__ float g_sb[10 * 256];           // per-output weight scales

// ---- PTX helpers -----------------------------------------------------------
__device__ __forceinline__ uint32_t smem_u32(const void* p) {
    uint32_t a;
    asm("{ .reg .u64 t; cvta.to.shared.u64 t, %1; cvt.u32.u64 %0, t; }" : "=r"(a) : "l"(p));
    return a;
}
__device__ __forceinline__ void ldsm4(uint32_t* r, uint32_t a) {
    asm volatile("ldmatrix.sync.aligned.m8n8.x4.shared.b16 {%0,%1,%2,%3}, [%4];"
                 : "=r"(r[0]), "=r"(r[1]), "=r"(r[2]), "=r"(r[3]) : "r"(a));
}
__device__ __forceinline__ void mma_s8(int* c, const uint32_t* a, uint32_t b0, uint32_t b1) {
    asm volatile("mma.sync.aligned.m16n8k32.row.col.s32.s8.s8.s32 "
                 "{%0,%1,%2,%3}, {%4,%5,%6,%7}, {%8,%9}, {%0,%1,%2,%3};"
                 : "+r"(c[0]), "+r"(c[1]), "+r"(c[2]), "+r"(c[3])
                 : "r"(a[0]), "r"(a[1]), "r"(a[2]), "r"(a[3]), "r"(b0), "r"(b1));
}
#define CP_ASYNC16(dst, src) \
    asm volatile("cp.async.cg.shared.global [%0], [%1], 16;" :: "r"(dst), "l"(src))
#define CP_COMMIT() asm volatile("cp.async.commit_group;")
#define CP_WAIT0()  asm volatile("cp.async.wait_group 0;")

// ---------------- prolog 1: triplane [pl][C][HW] -> [pl][HW][C] -------------
__global__ void transpose_trip(const float* __restrict__ in) {
    __shared__ float s[64][33];
    const int plane = blockIdx.y;
    const int hw0 = blockIdx.x * 32;
    const float* ip = in + (size_t)plane * CC * HH * WW;
    float* op = g_trip + (size_t)plane * HH * WW * CC;
    const int t = threadIdx.x, l32 = t & 31, grp = t >> 5;
#pragma unroll
    for (int i = 0; i < 8; i++) {
        int c = grp + i * 8;
        s[c][l32] = ip[(size_t)c * (HH * WW) + hw0 + l32];
    }
    __syncthreads();
    const int c2 = t & 63, r0 = t >> 6;
#pragma unroll
    for (int j = 0; j < 8; j++) {
        int r = r0 + j * 4;
        op[(size_t)(hw0 + r) * CC + c2] = s[c2][r];
    }
}

// ---------------- prolog 2: weight quantization -----------------------------
// one warp per (L, n). gmem chunk = L*2 + (k>>7), 64KB (d1 32KB | d0 32KB).
// within plane: blk = (n>>3)*8 + ((k>>4)&7); off = blk*128 + (n&7)*16 + (k&15).
// L0 region for k in [192,256) stays zero (g_wq zero-init).
__global__ void prep_weights(const float* __restrict__ w_in,
                             const float* __restrict__ w_hid) {
    const int lane = threadIdx.x & 31;
    const int id = blockIdx.x * 8 + (threadIdx.x >> 5);
    if (id >= 2560) return;
    const int L = id >> 8, n = id & 255;
    const int K = (L == 0) ? 192 : 256;
    float vals[8];
    float m = 0.0f;
#pragma unroll
    for (int j = 0; j < 8; j++) {
        const int k = lane + j * 32;
        float v = 0.0f;
        if (k < K)
            v = (L == 0) ? w_in[n * 192 + k] : w_hid[(size_t)(L - 1) * 65536 + n * 256 + k];
        vals[j] = v;
        m = fmaxf(m, fabsf(v));
    }
#pragma unroll
    for (int off = 16; off; off >>= 1) m = fmaxf(m, __shfl_xor_sync(0xFFFFFFFFu, m, off));
    const float inv = 16256.0f / fmaxf(m, 1e-30f);
    int8_t* gw = (int8_t*)g_wq;
#pragma unroll
    for (int j = 0; j < 8; j++) {
        const int k = lane + j * 32;
        if (k >= K) break;
        const float q = vals[j] * inv;
        const float d1f = rintf(q * 0.0078125f);
        const int d0 = __float2int_rn(q - 128.0f * d1f);
        const int d1 = (int)d1f;
        const size_t a = (size_t)(L * 2 + (k >> 7)) * 65536
                       + (size_t)(((n >> 3) * 8 + ((k >> 4) & 7)) * 128 + (n & 7) * 16 + (k & 15));
        gw[a] = (int8_t)d1;
        gw[a + 32768] = (int8_t)d0;
    }
    if (lane == 0) g_sb[id] = m * (1.0f / 16256.0f);
}

// ---------------- main fused decoder ----------------------------------------
__global__ void __launch_bounds__(NTH, 1)
decoder(const float* __restrict__ points,
        const float* __restrict__ b_in, const float* __restrict__ b_hid,
        const float* __restrict__ w_rgb, const float* __restrict__ b_rgb,
        const float* __restrict__ w_den, const float* __restrict__ b_den,
        const float* __restrict__ w_emb, const float* __restrict__ b_emb,
        float* __restrict__ out) {
    extern __shared__ char sm[];
    const uint32_t smb = smem_u32(sm);
    const int t = threadIdx.x, lane = t & 31, wid = t >> 5;
    const int wm = wid >> 2, wn = wid & 3;     // 4(M) x 4(N)
    const int g0 = blockIdx.x * PTS;
    const uint8_t* gw = (const uint8_t*)g_wq;

    // kick off weight chunk 0 (64KB; overlaps sampling)
    {
        const uint32_t dst = smb + SO_WBUF;
#pragma unroll
        for (int i = 0; i < 8; i++) {
            const int off = (t + i * NTH) * 16;
            CP_ASYNC16(dst + off, gw + off);
        }
        CP_COMMIT();
    }

    float* sbias = (float*)(sm + SO_SBIAS);
    float* sbs   = (float*)(sm + SO_SB);
    float* wht   = (float*)(sm + SO_WHT);
    float* rmax  = (float*)(sm + SO_RMAX);
    float* saA   = (float*)(sm + SO_SA);       // [2][64]
    float* invs  = (float*)(sm + SO_INV);
    int*   famax = (int*)(sm + SO_FAMAX);
    float* bhd   = (float*)(sm + SO_BHD);

    for (int i = t; i < 2560; i += NTH) {
        sbias[i] = (i < 256) ? b_in[i] : b_hid[i - 256];
        sbs[i] = g_sb[i];
    }
    for (int i = t; i < 256; i += NTH) {
        wht[i * 8 + 0] = w_rgb[i];        wht[i * 8 + 1] = w_rgb[256 + i];
        wht[i * 8 + 2] = w_rgb[512 + i];  wht[i * 8 + 3] = w_den[i];
        wht[i * 8 + 4] = w_emb[i];        wht[i * 8 + 5] = w_emb[256 + i];
        wht[i * 8 + 6] = w_emb[512 + i];  wht[i * 8 + 7] = 0.0f;
    }
    // zero BOTH A planes exactly (32KB; must NOT touch SO_WBUF — cp.async live)
    {
        uint4 z = {0u, 0u, 0u, 0u};
        uint4* ap = (uint4*)(sm + SO_A1);
#pragma unroll
        for (int i = 0; i < 4; i++) ap[t + i * NTH] = z;   // 2048 uint4 = 32KB
    }
    if (t < 64) famax[t] = 0;
    if (t < 3) bhd[t] = b_rgb[t];
    else if (t == 3) bhd[3] = b_den[0];
    else if (t < 7) bhd[t] = b_emb[t - 4];
    else if (t == 7) bhd[7] = 0.0f;
    __syncthreads();

    // ---- sampling phase A: compute feats (kept in regs), per-point |max| ----
    float frx[12], fry[12];
#pragma unroll
    for (int i = 0; i < 12; i++) {
        const int task = wid + i * 16;
        const int p = task / 3, pl = task - p * 3;
        const int g = g0 + p, b = g / NN;
        const float px = points[(size_t)g * 3 + 0];
        const float py = points[(size_t)g * 3 + 1];
        const float pz = points[(size_t)g * 3 + 2];
        float gx, gy;
        if (pl == 0)      { gx = px; gy = py; }
        else if (pl == 1) { gx = px; gy = pz; }
        else              { gx = py; gy = pz; }
        const float ix = (gx + 1.0f) * 0.5f * (float)(WW - 1);
        const float iy = (gy + 1.0f) * 0.5f * (float)(HH - 1);
        const float x0f = floorf(ix), y0f = floorf(iy);
        const float wx = ix - x0f, wy = iy - y0f;
        const int x0 = min(max((int)x0f, 0), WW - 1);
        const int x1 = min(max((int)x0f + 1, 0), WW - 1);
        const int y0 = min(max((int)y0f, 0), HH - 1);
        const int y1 = min(max((int)y0f + 1, 0), HH - 1);
        const float* base = g_trip + (size_t)(b * 3 + pl) * (HH * WW) * CC;
        const float2* c00 = (const float2*)(base + ((size_t)y0 * WW + x0) * CC);
        const float2* c01 = (const float2*)(base + ((size_t)y0 * WW + x1) * CC);
        const float2* c10 = (const float2*)(base + ((size_t)y1 * WW + x0) * CC);
        const float2* c11 = (const float2*)(base + ((size_t)y1 * WW + x1) * CC);
        const float w00 = (1.0f - wx) * (1.0f - wy), w01 = wx * (1.0f - wy);
        const float w10 = (1.0f - wx) * wy,          w11 = wx * wy;
        const float2 v00 = c00[lane], v01 = c01[lane];
        const float2 v10 = c10[lane], v11 = c11[lane];
        const float rx = v00.x * w00 + v01.x * w01 + v10.x * w10 + v11.x * w11;
        const float ry = v00.y * w00 + v01.y * w01 + v10.y * w10 + v11.y * w11;
        frx[i] = rx; fry[i] = ry;
        float am = fmaxf(fabsf(rx), fabsf(ry));
#pragma unroll
        for (int off = 16; off; off >>= 1) am = fmaxf(am, __shfl_xor_sync(0xFFFFFFFFu, am, off));
        if (lane == 0) atomicMax(&famax[p], __float_as_int(am));
    }
    __syncthreads();
    if (t < 64) {
        const float m = __int_as_float(famax[t]);
        saA[t] = m * (1.0f / 16256.0f);                 // sa[0][t]
        invs[t] = 16256.0f / fmaxf(m, 1e-20f);
    }
    __syncthreads();

    // ---- sampling phase B: digitize feats into A planes ---------------------
#pragma unroll
    for (int i = 0; i < 12; i++) {
        const int task = wid + i * 16;
        const int p = task / 3, pl = task - p * 3;
        const float inv = invs[p];
        const float qx = frx[i] * inv, qy = fry[i] * inv;
        const float d1xf = rintf(qx * 0.0078125f), d1yf = rintf(qy * 0.0078125f);
        const int d0x = __float2int_rn(qx - 128.0f * d1xf);
        const int d0y = __float2int_rn(qy - 128.0f * d1yf);
        const int d1x = (int)d1xf, d1y = (int)d1yf;
        const int col0 = pl * 64 + 2 * lane;
        const uint32_t u = (uint32_t)(col0 >> 4);
        const uint32_t base = (uint32_t)p * 256 + ((u ^ (p & 7)) << 4) + (col0 & 15);
        *(uint16_t*)(sm + SO_A1 + base) = (uint16_t)(((d1y & 0xFF) << 8) | (d1x & 0xFF));
        *(uint16_t*)(sm + SO_A0 + base) = (uint16_t)(((d0y & 0xFF) << 8) | (d0x & 0xFF));
    }
    __syncthreads();

    // ---- 10 layers ----------------------------------------------------------
    int gc = 0;
    for (int L = 0; L < 10; L++) {
        int acc1[8][4], accm[8][4];
#pragma unroll
        for (int ni = 0; ni < 8; ni++)
#pragma unroll
            for (int j = 0; j < 4; j++) { acc1[ni][j] = 0; accm[ni][j] = 0; }

        for (int ch = 0; ch < 2; ch++) {
            CP_WAIT0();
            __syncthreads();
            const uint32_t wb = smb + SO_WBUF + (gc & 1) * 65536;
            const int nxt = gc + 1;
            const uint32_t pdst = smb + SO_WBUF + (nxt & 1) * 65536;
            const uint8_t* psrc = gw + (size_t)nxt * 65536;
            const uint32_t tB = (uint32_t)(lane >> 3);
            const uint32_t rowB = (uint32_t)(lane & 7);

#pragma unroll
            for (int ks = 0; ks < 4; ks++) {
                if (nxt < NCHUNK_TOT) {       // spread prefetch: 2 cp.async / ks
#pragma unroll
                    for (int i = 0; i < 2; i++) {
                        const int off = (t + (ks * 2 + i) * NTH) * 16;
                        CP_ASYNC16(pdst + off, psrc + off);
                    }
                }
                // A fragments (d1, d0) for this k32 — warp tile M=16
                uint32_t a1[4], a0[4];
                {
                    const uint32_t rA = (uint32_t)(wm * 16 + (lane & 15));
                    const uint32_t uu = (uint32_t)(ch * 8 + ks * 2 + (lane >> 4));
                    const uint32_t aoff = rA * 256 + ((uu ^ (rA & 7)) << 4);
                    ldsm4(a1, smb + SO_A1 + aoff);
                    ldsm4(a0, smb + SO_A0 + aoff);
                }
                // B fragments + MMAs
#pragma unroll
                for (int nt2 = 0; nt2 < 4; nt2++) {
                    const uint32_t blk = (uint32_t)((wn * 8 + nt2 * 2 + (tB >> 1)) * 8
                                                    + ks * 2 + (tB & 1));
                    const uint32_t boff = blk * 128 + rowB * 16;
                    uint32_t bh[4], bl[4];
                    ldsm4(bh, wb + boff);
                    ldsm4(bl, wb + 32768 + boff);
                    mma_s8(acc1[nt2 * 2],     a1, bh[0], bh[1]);
                    mma_s8(acc1[nt2 * 2 + 1], a1, bh[2], bh[3]);
                    mma_s8(accm[nt2 * 2],     a1, bl[0], bl[1]);
                    mma_s8(accm[nt2 * 2 + 1], a1, bl[2], bl[3]);
                    mma_s8(accm[nt2 * 2],     a0, bh[0], bh[1]);
                    mma_s8(accm[nt2 * 2 + 1], a0, bh[2], bh[3]);
                }
            }
            if (nxt < NCHUNK_TOT) CP_COMMIT();
            gc++;
        }
        __syncthreads();   // all warps done reading A planes

        const float* sbl = sbs + L * 256;
        const float* bl_ = sbias + L * 256;
        const float* sap = saA + (L & 1) * 64;
        const int r1 = wm * 16 + (lane >> 2);

        if (L < 9) {
            // pass 1: dequant+relu, cache v in dead acc1/accm regs, row maxima
            float rmx0 = 0.0f, rmx1 = 0.0f;
            {
                const float s0 = sap[r1], s1 = sap[r1 + 8];
#pragma unroll
                for (int ni = 0; ni < 8; ni++) {
                    const int c0 = wn * 64 + ni * 8 + 2 * (lane & 3);
                    const float f0 = sbl[c0], f1 = sbl[c0 + 1];
                    const float b0 = bl_[c0], b1 = bl_[c0 + 1];
                    const float v0 = fmaxf(s0 * f0 * (16384.0f * (float)acc1[ni][0] + 128.0f * (float)accm[ni][0]) + b0, 0.0f);
                    const float v1 = fmaxf(s0 * f1 * (16384.0f * (float)acc1[ni][1] + 128.0f * (float)accm[ni][1]) + b1, 0.0f);
                    const float v2 = fmaxf(s1 * f0 * (16384.0f * (float)acc1[ni][2] + 128.0f * (float)accm[ni][2]) + b0, 0.0f);
                    const float v3 = fmaxf(s1 * f1 * (16384.0f * (float)acc1[ni][3] + 128.0f * (float)accm[ni][3]) + b1, 0.0f);
                    acc1[ni][0] = __float_as_int(v0); acc1[ni][1] = __float_as_int(v1);
                    acc1[ni][2] = __float_as_int(v2); acc1[ni][3] = __float_as_int(v3);
                    rmx0 = fmaxf(rmx0, fmaxf(v0, v1));
                    rmx1 = fmaxf(rmx1, fmaxf(v2, v3));
                }
            }
#pragma unroll
            for (int d = 1; d <= 2; d <<= 1) {
                rmx0 = fmaxf(rmx0, __shfl_xor_sync(0xFFFFFFFFu, rmx0, d));
                rmx1 = fmaxf(rmx1, __shfl_xor_sync(0xFFFFFFFFu, rmx1, d));
            }
            if ((lane & 3) == 0) {
                rmax[r1 * 4 + wn] = rmx0;
                rmax[(r1 + 8) * 4 + wn] = rmx1;
            }
            __syncthreads();
            // local row scales (no second barrier); t<64 stores sa for L+1
            const float m0 = fmaxf(fmaxf(rmax[r1 * 4], rmax[r1 * 4 + 1]),
                                   fmaxf(rmax[r1 * 4 + 2], rmax[r1 * 4 + 3]));
            const float m1 = fmaxf(fmaxf(rmax[(r1 + 8) * 4], rmax[(r1 + 8) * 4 + 1]),
                                   fmaxf(rmax[(r1 + 8) * 4 + 2], rmax[(r1 + 8) * 4 + 3]));
            const float i0 = 16256.0f / fmaxf(m0, 1e-20f);
            const float i1 = 16256.0f / fmaxf(m1, 1e-20f);
            if (t < 64) {
                const float mm = fmaxf(fmaxf(rmax[t * 4], rmax[t * 4 + 1]),
                                       fmaxf(rmax[t * 4 + 2], rmax[t * 4 + 3]));
                saA[((L + 1) & 1) * 64 + t] = mm * (1.0f / 16256.0f);
            }
            // pass 2: digitize cached v -> A planes
#pragma unroll
            for (int ni = 0; ni < 8; ni++) {
                const int c0 = wn * 64 + ni * 8 + 2 * (lane & 3);
                const float v0 = __int_as_float(acc1[ni][0]);
                const float v1 = __int_as_float(acc1[ni][1]);
                const float v2 = __int_as_float(acc1[ni][2]);
                const float v3 = __int_as_float(acc1[ni][3]);
                const float q0 = v0 * i0, q1 = v1 * i0, q2 = v2 * i1, q3 = v3 * i1;
                const float e0 = rintf(q0 * 0.0078125f), e1 = rintf(q1 * 0.0078125f);
                const float e2 = rintf(q2 * 0.0078125f), e3 = rintf(q3 * 0.0078125f);
                const int g0i = __float2int_rn(q0 - 128.0f * e0);
                const int g1i = __float2int_rn(q1 - 128.0f * e1);
                const int g2i = __float2int_rn(q2 - 128.0f * e2);
                const int g3i = __float2int_rn(q3 - 128.0f * e3);
                const uint32_t u = (uint32_t)(c0 >> 4);
                const uint32_t ba = (uint32_t)r1 * 256 + ((u ^ (r1 & 7)) << 4) + (c0 & 15);
                *(uint16_t*)(sm + SO_A1 + ba) = (uint16_t)((((int)e1 & 0xFF) << 8) | ((int)e0 & 0xFF));
                *(uint16_t*)(sm + SO_A0 + ba) = (uint16_t)(((g1i & 0xFF) << 8) | (g0i & 0xFF));
                *(uint16_t*)(sm + SO_A1 + ba + 2048) = (uint16_t)((((int)e3 & 0xFF) << 8) | ((int)e2 & 0xFF));
                *(uint16_t*)(sm + SO_A0 + ba + 2048) = (uint16_t)(((g3i & 0xFF) << 8) | (g2i & 0xFF));
            }
        } else {
            // final layer: dequant -> f32 acts at SO_ACT [64][256]
            float* act = (float*)(sm + SO_ACT);
            const float s0 = sap[r1], s1 = sap[r1 + 8];
#pragma unroll
            for (int ni = 0; ni < 8; ni++) {
                const int c0 = wn * 64 + ni * 8 + 2 * (lane & 3);
                const float f0 = sbl[c0], f1 = sbl[c0 + 1];
                const float b0 = bl_[c0], b1 = bl_[c0 + 1];
                act[r1 * 256 + c0]           = fmaxf(s0 * f0 * (16384.0f * (float)acc1[ni][0] + 128.0f * (float)accm[ni][0]) + b0, 0.0f);
                act[r1 * 256 + c0 + 1]       = fmaxf(s0 * f1 * (16384.0f * (float)acc1[ni][1] + 128.0f * (float)accm[ni][1]) + b1, 0.0f);
                act[(r1 + 8) * 256 + c0]     = fmaxf(s1 * f0 * (16384.0f * (float)acc1[ni][2] + 128.0f * (float)accm[ni][2]) + b0, 0.0f);
                act[(r1 + 8) * 256 + c0 + 1] = fmaxf(s1 * f1 * (16384.0f * (float)acc1[ni][3] + 128.0f * (float)accm[ni][3]) + b1, 0.0f);
            }
        }
        __syncthreads();
    }

    // ---- heads --------------------------------------------------------------
    const float* hf = (const float*)(sm + SO_ACT);
    for (int task = wid; task < PTS * 7; task += 16) {
        const int p = task & 63;
        const int j = task >> 6;
        const float4* hp = (const float4*)(hf + p * 256);
        float s = 0.0f;
#pragma unroll
        for (int ii = 0; ii < 2; ii++) {
            const float4 hv = hp[lane + ii * 32];
            const int c0 = (lane + ii * 32) * 4;
            s += hv.x * wht[(c0 + 0) * 8 + j] + hv.y * wht[(c0 + 1) * 8 + j]
               + hv.z * wht[(c0 + 2) * 8 + j] + hv.w * wht[(c0 + 3) * 8 + j];
        }
#pragma unroll
        for (int off = 16; off; off >>= 1) s += __shfl_xor_sync(0xFFFFFFFFu, s, off);
        if (lane == 0) {
            s += bhd[j];
            const int g = g0 + p;
            if (j < 3)
                out[(size_t)g * 3 + j] = 1.0f / (1.0f + expf(-s));
            else if (j == 3)
                out[(size_t)BB * NN * 3 + g] = s;
            else
                out[(size_t)BB * NN * 4 + (size_t)g * 3 + (j - 4)] = s;
        }
    }
}

// ---------------------------------------------------------------------------
extern "C" void kernel_launch(void* const* d_in, const int* in_sizes, int n_in,
                              void* d_out, int out_size) {
    const float* triplane = (const float*)d_in[0];
    const float* points   = (const float*)d_in[1];
    const float* w_in     = (const float*)d_in[2];
    const float* b_in     = (const float*)d_in[3];
    const float* w_hid    = (const float*)d_in[4];
    const float* b_hid    = (const float*)d_in[5];
    const float* w_rgb    = (const float*)d_in[6];
    const float* b_rgb    = (const float*)d_in[7];
    const float* w_den    = (const float*)d_in[8];
    const float* b_den    = (const float*)d_in[9];
    const float* w_emb    = (const float*)d_in[10];
    const float* b_emb    = (const float*)d_in[11];
    float* out = (float*)d_out;

    transpose_trip<<<dim3((HH * WW) / 32, BB * 3), 256>>>(triplane);
    prep_weights<<<320, 256>>>(w_in, w_hid);

    cudaFuncSetAttribute(decoder, cudaFuncAttributeMaxDynamicSharedMemorySize, SMEM_TOT);
    decoder<<<(BB * NN) / PTS, NTH, SMEM_TOT>>>(
        points, b_in, b_hid, w_rgb, b_rgb, w_den, b_den, w_emb, b_emb, out);
}

// round 12
// speedup vs baseline: 1.2540x; 1.0253x over previous
#include <cuda_runtime.h>
#include <math.h>
#include <stdint.h>

// ---------------------------------------------------------------------------
// TriplaneDecoder via int8 double-digit mma.sync (m16n8k32.s8) — compute_100.
// x = s*(d1*128 + d0). D = sa*sb*(16384*S11 + 128*S1m), S1m = d1a.d0b+d0a.d1b.
// R12: epilogue IMAD form (k = 128*a1+am, scales pre-x128); syncs 3->1 per
// layer epilogue (rmax barrier only). 16 warps 4Mx4N tile 16x64; 64KB
// double-buffered chunks (20 total), L0 zero-padded to K=256.
// ---------------------------------------------------------------------------

#define BB 4
#define NN 100000
#define CC 64
#define HH 256
#define WW 256
#define PTS 64
#define NTH 512
#define NCHUNK_TOT 20     // 10 layers x 2 chunks x 64KB

// smem byte offsets
#define SO_A1    0        // A d1 plane: 64 x 256 s8 (16KB)
#define SO_A0    16384    // A d0 plane (16KB)
#define SO_WBUF  32768    // 2 x 64KB weight chunk buffers (d1 32KB | d0 32KB)
#define SO_ACT   0        // overlay (final f32 acts 64x256 = 64KB)
#define SO_SBIAS 163840   // biases 10*256 f32
#define SO_SB    174080   // weight col scales x128 10*256 f32
#define SO_WHT   184320   // head weights [256][8] f32
#define SO_RMAX  192512   // rowmax partials [64][4] f32
#define SO_SA    193536   // A row scales, ping-pong [2][64] f32
#define SO_INV   194048   // inv scale [64] f32 (sampling only)
#define SO_FAMAX 194304   // feat |max| bits [64] u32
#define SO_BHD   194560   // head biases [8]
#define SMEM_TOT 194592

__device__ float g_trip[(size_t)BB * 3 * HH * WW * CC];
__device__ uint4 g_wq[1310720 / 16];       // 20 x 64KB chunks (zero-init pads L0)
__device__ float g_sb[10 * 256];           // per-output weight scales

// ---- PTX helpers -----------------------------------------------------------
__device__ __forceinline__ uint32_t smem_u32(const void* p) {
    uint32_t a;
    asm("{ .reg .u64 t; cvta.to.shared.u64 t, %1; cvt.u32.u64 %0, t; }" : "=r"(a) : "l"(p));
    return a;
}
__device__ __forceinline__ void ldsm4(uint32_t* r, uint32_t a) {
    asm volatile("ldmatrix.sync.aligned.m8n8.x4.shared.b16 {%0,%1,%2,%3}, [%4];"
                 : "=r"(r[0]), "=r"(r[1]), "=r"(r[2]), "=r"(r[3]) : "r"(a));
}
__device__ __forceinline__ void mma_s8(int* c, const uint32_t* a, uint32_t b0, uint32_t b1) {
    asm volatile("mma.sync.aligned.m16n8k32.row.col.s32.s8.s8.s32 "
                 "{%0,%1,%2,%3}, {%4,%5,%6,%7}, {%8,%9}, {%0,%1,%2,%3};"
                 : "+r"(c[0]), "+r"(c[1]), "+r"(c[2]), "+r"(c[3])
                 : "r"(a[0]), "r"(a[1]), "r"(a[2]), "r"(a[3]), "r"(b0), "r"(b1));
}
#define CP_ASYNC16(dst, src) \
    asm volatile("cp.async.cg.shared.global [%0], [%1], 16;" :: "r"(dst), "l"(src))
#define CP_COMMIT() asm volatile("cp.async.commit_group;")
#define CP_WAIT0()  asm volatile("cp.async.wait_group 0;")

// ---------------- prolog 1: triplane [pl][C][HW] -> [pl][HW][C] -------------
__global__ void transpose_trip(const float* __restrict__ in) {
    __shared__ float s[64][33];
    const int plane = blockIdx.y;
    const int hw0 = blockIdx.x * 32;
    const float* ip = in + (size_t)plane * CC * HH * WW;
    float* op = g_trip + (size_t)plane * HH * WW * CC;
    const int t = threadIdx.x, l32 = t & 31, grp = t >> 5;
#pragma unroll
    for (int i = 0; i < 8; i++) {
        int c = grp + i * 8;
        s[c][l32] = ip[(size_t)c * (HH * WW) + hw0 + l32];
    }
    __syncthreads();
    const int c2 = t & 63, r0 = t >> 6;
#pragma unroll
    for (int j = 0; j < 8; j++) {
        int r = r0 + j * 4;
        op[(size_t)(hw0 + r) * CC + c2] = s[c2][r];
    }
}

// ---------------- prolog 2: weight quantization -----------------------------
__global__ void prep_weights(const float* __restrict__ w_in,
                             const float* __restrict__ w_hid) {
    const int lane = threadIdx.x & 31;
    const int id = blockIdx.x * 8 + (threadIdx.x >> 5);
    if (id >= 2560) return;
    const int L = id >> 8, n = id & 255;
    const int K = (L == 0) ? 192 : 256;
    float vals[8];
    float m = 0.0f;
#pragma unroll
    for (int j = 0; j < 8; j++) {
        const int k = lane + j * 32;
        float v = 0.0f;
        if (k < K)
            v = (L == 0) ? w_in[n * 192 + k] : w_hid[(size_t)(L - 1) * 65536 + n * 256 + k];
        vals[j] = v;
        m = fmaxf(m, fabsf(v));
    }
#pragma unroll
    for (int off = 16; off; off >>= 1) m = fmaxf(m, __shfl_xor_sync(0xFFFFFFFFu, m, off));
    const float inv = 16256.0f / fmaxf(m, 1e-30f);
    int8_t* gw = (int8_t*)g_wq;
#pragma unroll
    for (int j = 0; j < 8; j++) {
        const int k = lane + j * 32;
        if (k >= K) break;
        const float q = vals[j] * inv;
        const float d1f = rintf(q * 0.0078125f);
        const int d0 = __float2int_rn(q - 128.0f * d1f);
        const int d1 = (int)d1f;
        const size_t a = (size_t)(L * 2 + (k >> 7)) * 65536
                       + (size_t)(((n >> 3) * 8 + ((k >> 4) & 7)) * 128 + (n & 7) * 16 + (k & 15));
        gw[a] = (int8_t)d1;
        gw[a + 32768] = (int8_t)d0;
    }
    if (lane == 0) g_sb[id] = m * (1.0f / 16256.0f);
}

// ---------------- main fused decoder ----------------------------------------
__global__ void __launch_bounds__(NTH, 1)
decoder(const float* __restrict__ points,
        const float* __restrict__ b_in, const float* __restrict__ b_hid,
        const float* __restrict__ w_rgb, const float* __restrict__ b_rgb,
        const float* __restrict__ w_den, const float* __restrict__ b_den,
        const float* __restrict__ w_emb, const float* __restrict__ b_emb,
        float* __restrict__ out) {
    extern __shared__ char sm[];
    const uint32_t smb = smem_u32(sm);
    const int t = threadIdx.x, lane = t & 31, wid = t >> 5;
    const int wm = wid >> 2, wn = wid & 3;     // 4(M) x 4(N)
    const int g0 = blockIdx.x * PTS;
    const uint8_t* gw = (const uint8_t*)g_wq;

    // kick off weight chunk 0 (64KB; overlaps sampling)
    {
        const uint32_t dst = smb + SO_WBUF;
#pragma unroll
        for (int i = 0; i < 8; i++) {
            const int off = (t + i * NTH) * 16;
            CP_ASYNC16(dst + off, gw + off);
        }
        CP_COMMIT();
    }

    float* sbias = (float*)(sm + SO_SBIAS);
    float* sbs   = (float*)(sm + SO_SB);
    float* wht   = (float*)(sm + SO_WHT);
    float* rmax  = (float*)(sm + SO_RMAX);
    float* saA   = (float*)(sm + SO_SA);       // [2][64]
    float* invs  = (float*)(sm + SO_INV);
    int*   famax = (int*)(sm + SO_FAMAX);
    float* bhd   = (float*)(sm + SO_BHD);

    for (int i = t; i < 2560; i += NTH) {
        sbias[i] = (i < 256) ? b_in[i] : b_hid[i - 256];
        sbs[i] = g_sb[i] * 128.0f;            // pre-x128 for IMAD dequant form
    }
    for (int i = t; i < 256; i += NTH) {
        wht[i * 8 + 0] = w_rgb[i];        wht[i * 8 + 1] = w_rgb[256 + i];
        wht[i * 8 + 2] = w_rgb[512 + i];  wht[i * 8 + 3] = w_den[i];
        wht[i * 8 + 4] = w_emb[i];        wht[i * 8 + 5] = w_emb[256 + i];
        wht[i * 8 + 6] = w_emb[512 + i];  wht[i * 8 + 7] = 0.0f;
    }
    // zero BOTH A planes exactly (32KB; must NOT touch SO_WBUF — cp.async live)
    {
        uint4 z = {0u, 0u, 0u, 0u};
        uint4* ap = (uint4*)(sm + SO_A1);
#pragma unroll
        for (int i = 0; i < 4; i++) ap[t + i * NTH] = z;   // 2048 uint4 = 32KB
    }
    if (t < 64) famax[t] = 0;
    if (t < 3) bhd[t] = b_rgb[t];
    else if (t == 3) bhd[3] = b_den[0];
    else if (t < 7) bhd[t] = b_emb[t - 4];
    else if (t == 7) bhd[7] = 0.0f;
    __syncthreads();

    // ---- sampling phase A ---------------------------------------------------
    float frx[12], fry[12];
#pragma unroll
    for (int i = 0; i < 12; i++) {
        const int task = wid + i * 16;
        const int p = task / 3, pl = task - p * 3;
        const int g = g0 + p, b = g / NN;
        const float px = points[(size_t)g * 3 + 0];
        const float py = points[(size_t)g * 3 + 1];
        const float pz = points[(size_t)g * 3 + 2];
        float gx, gy;
        if (pl == 0)      { gx = px; gy = py; }
        else if (pl == 1) { gx = px; gy = pz; }
        else              { gx = py; gy = pz; }
        const float ix = (gx + 1.0f) * 0.5f * (float)(WW - 1);
        const float iy = (gy + 1.0f) * 0.5f * (float)(HH - 1);
        const float x0f = floorf(ix), y0f = floorf(iy);
        const float wx = ix - x0f, wy = iy - y0f;
        const int x0 = min(max((int)x0f, 0), WW - 1);
        const int x1 = min(max((int)x0f + 1, 0), WW - 1);
        const int y0 = min(max((int)y0f, 0), HH - 1);
        const int y1 = min(max((int)y0f + 1, 0), HH - 1);
        const float* base = g_trip + (size_t)(b * 3 + pl) * (HH * WW) * CC;
        const float2* c00 = (const float2*)(base + ((size_t)y0 * WW + x0) * CC);
        const float2* c01 = (const float2*)(base + ((size_t)y0 * WW + x1) * CC);
        const float2* c10 = (const float2*)(base + ((size_t)y1 * WW + x0) * CC);
        const float2* c11 = (const float2*)(base + ((size_t)y1 * WW + x1) * CC);
        const float w00 = (1.0f - wx) * (1.0f - wy), w01 = wx * (1.0f - wy);
        const float w10 = (1.0f - wx) * wy,          w11 = wx * wy;
        const float2 v00 = c00[lane], v01 = c01[lane];
        const float2 v10 = c10[lane], v11 = c11[lane];
        const float rx = v00.x * w00 + v01.x * w01 + v10.x * w10 + v11.x * w11;
        const float ry = v00.y * w00 + v01.y * w01 + v10.y * w10 + v11.y * w11;
        frx[i] = rx; fry[i] = ry;
        float am = fmaxf(fabsf(rx), fabsf(ry));
#pragma unroll
        for (int off = 16; off; off >>= 1) am = fmaxf(am, __shfl_xor_sync(0xFFFFFFFFu, am, off));
        if (lane == 0) atomicMax(&famax[p], __float_as_int(am));
    }
    __syncthreads();
    if (t < 64) {
        const float m = __int_as_float(famax[t]);
        saA[t] = m * (1.0f / 16256.0f);
        invs[t] = 16256.0f / fmaxf(m, 1e-20f);
    }
    __syncthreads();

    // ---- sampling phase B: digitize feats into A planes ---------------------
#pragma unroll
    for (int i = 0; i < 12; i++) {
        const int task = wid + i * 16;
        const int p = task / 3, pl = task - p * 3;
        const float inv = invs[p];
        const float qx = frx[i] * inv, qy = fry[i] * inv;
        const float d1xf = rintf(qx * 0.0078125f), d1yf = rintf(qy * 0.0078125f);
        const int d0x = __float2int_rn(qx - 128.0f * d1xf);
        const int d0y = __float2int_rn(qy - 128.0f * d1yf);
        const int d1x = (int)d1xf, d1y = (int)d1yf;
        const int col0 = pl * 64 + 2 * lane;
        const uint32_t u = (uint32_t)(col0 >> 4);
        const uint32_t base = (uint32_t)p * 256 + ((u ^ (p & 7)) << 4) + (col0 & 15);
        *(uint16_t*)(sm + SO_A1 + base) = (uint16_t)(((d1y & 0xFF) << 8) | (d1x & 0xFF));
        *(uint16_t*)(sm + SO_A0 + base) = (uint16_t)(((d0y & 0xFF) << 8) | (d0x & 0xFF));
    }
    __syncthreads();

    // ---- 10 layers ----------------------------------------------------------
    int gc = 0;
    for (int L = 0; L < 10; L++) {
        int acc1[8][4], accm[8][4];
#pragma unroll
        for (int ni = 0; ni < 8; ni++)
#pragma unroll
            for (int j = 0; j < 4; j++) { acc1[ni][j] = 0; accm[ni][j] = 0; }

        for (int ch = 0; ch < 2; ch++) {
            CP_WAIT0();
            __syncthreads();
            const uint32_t wb = smb + SO_WBUF + (gc & 1) * 65536;
            const int nxt = gc + 1;
            const uint32_t pdst = smb + SO_WBUF + (nxt & 1) * 65536;
            const uint8_t* psrc = gw + (size_t)nxt * 65536;
            const uint32_t tB = (uint32_t)(lane >> 3);
            const uint32_t rowB = (uint32_t)(lane & 7);

#pragma unroll
            for (int ks = 0; ks < 4; ks++) {
                if (nxt < NCHUNK_TOT) {
#pragma unroll
                    for (int i = 0; i < 2; i++) {
                        const int off = (t + (ks * 2 + i) * NTH) * 16;
                        CP_ASYNC16(pdst + off, psrc + off);
                    }
                }
                uint32_t a1[4], a0[4];
                {
                    const uint32_t rA = (uint32_t)(wm * 16 + (lane & 15));
                    const uint32_t uu = (uint32_t)(ch * 8 + ks * 2 + (lane >> 4));
                    const uint32_t aoff = rA * 256 + ((uu ^ (rA & 7)) << 4);
                    ldsm4(a1, smb + SO_A1 + aoff);
                    ldsm4(a0, smb + SO_A0 + aoff);
                }
#pragma unroll
                for (int nt2 = 0; nt2 < 4; nt2++) {
                    const uint32_t blk = (uint32_t)((wn * 8 + nt2 * 2 + (tB >> 1)) * 8
                                                    + ks * 2 + (tB & 1));
                    const uint32_t boff = blk * 128 + rowB * 16;
                    uint32_t bh[4], bl[4];
                    ldsm4(bh, wb + boff);
                    ldsm4(bl, wb + 32768 + boff);
                    mma_s8(acc1[nt2 * 2],     a1, bh[0], bh[1]);
                    mma_s8(acc1[nt2 * 2 + 1], a1, bh[2], bh[3]);
                    mma_s8(accm[nt2 * 2],     a1, bl[0], bl[1]);
                    mma_s8(accm[nt2 * 2 + 1], a1, bl[2], bl[3]);
                    mma_s8(accm[nt2 * 2],     a0, bh[0], bh[1]);
                    mma_s8(accm[nt2 * 2 + 1], a0, bh[2], bh[3]);
                }
            }
            if (nxt < NCHUNK_TOT) CP_COMMIT();
            gc++;
        }

        const float* sbl = sbs + L * 256;     // pre-x128 weight scales
        const float* bl_ = sbias + L * 256;
        const float* sap = saA + (L & 1) * 64;
        const int r1 = wm * 16 + (lane >> 2);

        if (L < 9) {
            // pass 1 (no sync needed first: registers + stable smem only):
            // dequant via IMAD form, cache v in dead acc1 regs, row maxima.
            float rmx0 = 0.0f, rmx1 = 0.0f;
            {
                const float s0 = sap[r1], s1 = sap[r1 + 8];
#pragma unroll
                for (int ni = 0; ni < 8; ni++) {
                    const int c0 = wn * 64 + ni * 8 + 2 * (lane & 3);
                    const float sf00 = s0 * sbl[c0], sf01 = s0 * sbl[c0 + 1];
                    const float sf10 = s1 * sbl[c0], sf11 = s1 * sbl[c0 + 1];
                    const float b0 = bl_[c0], b1 = bl_[c0 + 1];
                    const int k0 = acc1[ni][0] * 128 + accm[ni][0];
                    const int k1 = acc1[ni][1] * 128 + accm[ni][1];
                    const int k2 = acc1[ni][2] * 128 + accm[ni][2];
                    const int k3 = acc1[ni][3] * 128 + accm[ni][3];
                    const float v0 = fmaxf(fmaf((float)k0, sf00, b0), 0.0f);
                    const float v1 = fmaxf(fmaf((float)k1, sf01, b1), 0.0f);
                    const float v2 = fmaxf(fmaf((float)k2, sf10, b0), 0.0f);
                    const float v3 = fmaxf(fmaf((float)k3, sf11, b1), 0.0f);
                    acc1[ni][0] = __float_as_int(v0); acc1[ni][1] = __float_as_int(v1);
                    acc1[ni][2] = __float_as_int(v2); acc1[ni][3] = __float_as_int(v3);
                    rmx0 = fmaxf(rmx0, fmaxf(v0, v1));
                    rmx1 = fmaxf(rmx1, fmaxf(v2, v3));
                }
            }
#pragma unroll
            for (int d = 1; d <= 2; d <<= 1) {
                rmx0 = fmaxf(rmx0, __shfl_xor_sync(0xFFFFFFFFu, rmx0, d));
                rmx1 = fmaxf(rmx1, __shfl_xor_sync(0xFFFFFFFFu, rmx1, d));
            }
            if ((lane & 3) == 0) {
                rmax[r1 * 4 + wn] = rmx0;
                rmax[(r1 + 8) * 4 + wn] = rmx1;
            }
            __syncthreads();                   // the ONLY epilogue barrier
            if (t < 64) {
                const float mm = fmaxf(fmaxf(rmax[t * 4], rmax[t * 4 + 1]),
                                       fmaxf(rmax[t * 4 + 2], rmax[t * 4 + 3]));
                saA[((L + 1) & 1) * 64 + t] = mm * (1.0f / 16256.0f);
            }
            const float m0 = fmaxf(fmaxf(rmax[r1 * 4], rmax[r1 * 4 + 1]),
                                   fmaxf(rmax[r1 * 4 + 2], rmax[r1 * 4 + 3]));
            const float m1 = fmaxf(fmaxf(rmax[(r1 + 8) * 4], rmax[(r1 + 8) * 4 + 1]),
                                   fmaxf(rmax[(r1 + 8) * 4 + 2], rmax[(r1 + 8) * 4 + 3]));
            const float i0 = 16256.0f / fmaxf(m0, 1e-20f);
            const float i1 = 16256.0f / fmaxf(m1, 1e-20f);
            // pass 2: digitize cached v -> A planes (next chunk's start-sync
            // orders these stores before any ldsm of layer L+1)
#pragma unroll
            for (int ni = 0; ni < 8; ni++) {
                const int c0 = wn * 64 + ni * 8 + 2 * (lane & 3);
                const float v0 = __int_as_float(acc1[ni][0]);
                const float v1 = __int_as_float(acc1[ni][1]);
                const float v2 = __int_as_float(acc1[ni][2]);
                const float v3 = __int_as_float(acc1[ni][3]);
                const float q0 = v0 * i0, q1 = v1 * i0, q2 = v2 * i1, q3 = v3 * i1;
                const float e0 = rintf(q0 * 0.0078125f), e1 = rintf(q1 * 0.0078125f);
                const float e2 = rintf(q2 * 0.0078125f), e3 = rintf(q3 * 0.0078125f);
                const int g0i = __float2int_rn(q0 - 128.0f * e0);
                const int g1i = __float2int_rn(q1 - 128.0f * e1);
                const int g2i = __float2int_rn(q2 - 128.0f * e2);
                const int g3i = __float2int_rn(q3 - 128.0f * e3);
                const uint32_t u = (uint32_t)(c0 >> 4);
                const uint32_t ba = (uint32_t)r1 * 256 + ((u ^ (r1 & 7)) << 4) + (c0 & 15);
                *(uint16_t*)(sm + SO_A1 + ba) = (uint16_t)((((int)e1 & 0xFF) << 8) | ((int)e0 & 0xFF));
                *(uint16_t*)(sm + SO_A0 + ba) = (uint16_t)(((g1i & 0xFF) << 8) | (g0i & 0xFF));
                *(uint16_t*)(sm + SO_A1 + ba + 2048) = (uint16_t)((((int)e3 & 0xFF) << 8) | ((int)e2 & 0xFF));
                *(uint16_t*)(sm + SO_A0 + ba + 2048) = (uint16_t)(((g3i & 0xFF) << 8) | (g2i & 0xFF));
            }
        } else {
            __syncthreads();                   // all A-plane ldsm reads done
            // final layer: dequant -> f32 acts at SO_ACT [64][256] (overlay)
            float* act = (float*)(sm + SO_ACT);
            const float s0 = sap[r1], s1 = sap[r1 + 8];
#pragma unroll
            for (int ni = 0; ni < 8; ni++) {
                const int c0 = wn * 64 + ni * 8 + 2 * (lane & 3);
                const float sf00 = s0 * sbl[c0], sf01 = s0 * sbl[c0 + 1];
                const float sf10 = s1 * sbl[c0], sf11 = s1 * sbl[c0 + 1];
                const float b0 = bl_[c0], b1 = bl_[c0 + 1];
                const int k0 = acc1[ni][0] * 128 + accm[ni][0];
                const int k1 = acc1[ni][1] * 128 + accm[ni][1];
                const int k2 = acc1[ni][2] * 128 + accm[ni][2];
                const int k3 = acc1[ni][3] * 128 + accm[ni][3];
                act[r1 * 256 + c0]           = fmaxf(fmaf((float)k0, sf00, b0), 0.0f);
                act[r1 * 256 + c0 + 1]       = fmaxf(fmaf((float)k1, sf01, b1), 0.0f);
                act[(r1 + 8) * 256 + c0]     = fmaxf(fmaf((float)k2, sf10, b0), 0.0f);
                act[(r1 + 8) * 256 + c0 + 1] = fmaxf(fmaf((float)k3, sf11, b1), 0.0f);
            }
            __syncthreads();                   // acts visible for heads
        }
    }

    // ---- heads --------------------------------------------------------------
    const float* hf = (const float*)(sm + SO_ACT);
    for (int task = wid; task < PTS * 7; task += 16) {
        const int p = task & 63;
        const int j = task >> 6;
        const float4* hp = (const float4*)(hf + p * 256);
        float s = 0.0f;
#pragma unroll
        for (int ii = 0; ii < 2; ii++) {
            const float4 hv = hp[lane + ii * 32];
            const int c0 = (lane + ii * 32) * 4;
            s += hv.x * wht[(c0 + 0) * 8 + j] + hv.y * wht[(c0 + 1) * 8 + j]
               + hv.z * wht[(c0 + 2) * 8 + j] + hv.w * wht[(c0 + 3) * 8 + j];
        }
#pragma unroll
        for (int off = 16; off; off >>= 1) s += __shfl_xor_sync(0xFFFFFFFFu, s, off);
        if (lane == 0) {
            s += bhd[j];
            const int g = g0 + p;
            if (j < 3)
                out[(size_t)g * 3 + j] = 1.0f / (1.0f + expf(-s));
            else if (j == 3)
                out[(size_t)BB * NN * 3 + g] = s;
            else
                out[(size_t)BB * NN * 4 + (size_t)g * 3 + (j - 4)] = s;
        }
    }
}

// ---------------------------------------------------------------------------
extern "C" void kernel_launch(void* const* d_in, const int* in_sizes, int n_in,
                              void* d_out, int out_size) {
    const float* triplane = (const float*)d_in[0];
    const float* points   = (const float*)d_in[1];
    const float* w_in     = (const float*)d_in[2];
    const float* b_in     = (const float*)d_in[3];
    const float* w_hid    = (const float*)d_in[4];
    const float* b_hid    = (const float*)d_in[5];
    const float* w_rgb    = (const float*)d_in[6];
    const float* b_rgb    = (const float*)d_in[7];
    const float* w_den    = (const float*)d_in[8];
    const float* b_den    = (const float*)d_in[9];
    const float* w_emb    = (const float*)d_in[10];
    const float* b_emb    = (const float*)d_in[11];
    float* out = (float*)d_out;

    transpose_trip<<<dim3((HH * WW) / 32, BB * 3), 256>>>(triplane);
    prep_weights<<<320, 256>>>(w_in, w_hid);

    cudaFuncSetAttribute(decoder, cudaFuncAttributeMaxDynamicSharedMemorySize, SMEM_TOT);
    decoder<<<(BB * NN) / PTS, NTH, SMEM_TOT>>>(
        points, b_in, b_hid, w_rgb, b_rgb, w_den, b_den, w_emb, b_emb, out);
}

// round 13
// speedup vs baseline: 1.3206x; 1.0531x over previous
#include <cuda_runtime.h>
#include <math.h>
#include <stdint.h>

// ---------------------------------------------------------------------------
// TriplaneDecoder via int8 double-digit mma.sync (m16n8k32.s8) — compute_100.
// x = s*(d1*128 + d0). D = sa*sb*(16384*S11 + 128*S1m), S1m = d1a.d0b+d0a.d1b.
// R13: (1) chunk prefetch issued fully at chunk top (covers L2 latency;
// spread issue could expose cp.async completion at next chunk's wait);
// (2) integer digitize qi=rn(q), d1=(qi+64)>>7, d0=qi-128*d1 — ALU+FMA
// dual-issue, exact in range. 16 warps 4Mx4N tile 16x64; 64KB chunks x20.
// ---------------------------------------------------------------------------

#define BB 4
#define NN 100000
#define CC 64
#define HH 256
#define WW 256
#define PTS 64
#define NTH 512
#define NCHUNK_TOT 20     // 10 layers x 2 chunks x 64KB

// smem byte offsets
#define SO_A1    0        // A d1 plane: 64 x 256 s8 (16KB)
#define SO_A0    16384    // A d0 plane (16KB)
#define SO_WBUF  32768    // 2 x 64KB weight chunk buffers (d1 32KB | d0 32KB)
#define SO_ACT   0        // overlay (final f32 acts 64x256 = 64KB)
#define SO_SBIAS 163840   // biases 10*256 f32
#define SO_SB    174080   // weight col scales x128 10*256 f32
#define SO_WHT   184320   // head weights [256][8] f32
#define SO_RMAX  192512   // rowmax partials [64][4] f32
#define SO_SA    193536   // A row scales, ping-pong [2][64] f32
#define SO_INV   194048   // inv scale [64] f32 (sampling only)
#define SO_FAMAX 194304   // feat |max| bits [64] u32
#define SO_BHD   194560   // head biases [8]
#define SMEM_TOT 194592

__device__ float g_trip[(size_t)BB * 3 * HH * WW * CC];
__device__ uint4 g_wq[1310720 / 16];       // 20 x 64KB chunks (zero-init pads L0)
__device__ float g_sb[10 * 256];           // per-output weight scales

// ---- PTX helpers -----------------------------------------------------------
__device__ __forceinline__ uint32_t smem_u32(const void* p) {
    uint32_t a;
    asm("{ .reg .u64 t; cvta.to.shared.u64 t, %1; cvt.u32.u64 %0, t; }" : "=r"(a) : "l"(p));
    return a;
}
__device__ __forceinline__ void ldsm4(uint32_t* r, uint32_t a) {
    asm volatile("ldmatrix.sync.aligned.m8n8.x4.shared.b16 {%0,%1,%2,%3}, [%4];"
                 : "=r"(r[0]), "=r"(r[1]), "=r"(r[2]), "=r"(r[3]) : "r"(a));
}
__device__ __forceinline__ void mma_s8(int* c, const uint32_t* a, uint32_t b0, uint32_t b1) {
    asm volatile("mma.sync.aligned.m16n8k32.row.col.s32.s8.s8.s32 "
                 "{%0,%1,%2,%3}, {%4,%5,%6,%7}, {%8,%9}, {%0,%1,%2,%3};"
                 : "+r"(c[0]), "+r"(c[1]), "+r"(c[2]), "+r"(c[3])
                 : "r"(a[0]), "r"(a[1]), "r"(a[2]), "r"(a[3]), "r"(b0), "r"(b1));
}
#define CP_ASYNC16(dst, src) \
    asm volatile("cp.async.cg.shared.global [%0], [%1], 16;" :: "r"(dst), "l"(src))
#define CP_COMMIT() asm volatile("cp.async.commit_group;")
#define CP_WAIT0()  asm volatile("cp.async.wait_group 0;")

// integer digitize: qi in [-16256,16256] -> d1 in [-127,127], d0 in [-64,63]
__device__ __forceinline__ void digitize(float q, int& d1, int& d0) {
    const int qi = __float2int_rn(q);
    d1 = (qi + 64) >> 7;
    d0 = qi - (d1 << 7);
}

// ---------------- prolog 1: triplane [pl][C][HW] -> [pl][HW][C] -------------
__global__ void transpose_trip(const float* __restrict__ in) {
    __shared__ float s[64][33];
    const int plane = blockIdx.y;
    const int hw0 = blockIdx.x * 32;
    const float* ip = in + (size_t)plane * CC * HH * WW;
    float* op = g_trip + (size_t)plane * HH * WW * CC;
    const int t = threadIdx.x, l32 = t & 31, grp = t >> 5;
#pragma unroll
    for (int i = 0; i < 8; i++) {
        int c = grp + i * 8;
        s[c][l32] = ip[(size_t)c * (HH * WW) + hw0 + l32];
    }
    __syncthreads();
    const int c2 = t & 63, r0 = t >> 6;
#pragma unroll
    for (int j = 0; j < 8; j++) {
        int r = r0 + j * 4;
        op[(size_t)(hw0 + r) * CC + c2] = s[c2][r];
    }
}

// ---------------- prolog 2: weight quantization -----------------------------
__global__ void prep_weights(const float* __restrict__ w_in,
                             const float* __restrict__ w_hid) {
    const int lane = threadIdx.x & 31;
    const int id = blockIdx.x * 8 + (threadIdx.x >> 5);
    if (id >= 2560) return;
    const int L = id >> 8, n = id & 255;
    const int K = (L == 0) ? 192 : 256;
    float vals[8];
    float m = 0.0f;
#pragma unroll
    for (int j = 0; j < 8; j++) {
        const int k = lane + j * 32;
        float v = 0.0f;
        if (k < K)
            v = (L == 0) ? w_in[n * 192 + k] : w_hid[(size_t)(L - 1) * 65536 + n * 256 + k];
        vals[j] = v;
        m = fmaxf(m, fabsf(v));
    }
#pragma unroll
    for (int off = 16; off; off >>= 1) m = fmaxf(m, __shfl_xor_sync(0xFFFFFFFFu, m, off));
    const float inv = 16256.0f / fmaxf(m, 1e-30f);
    int8_t* gw = (int8_t*)g_wq;
#pragma unroll
    for (int j = 0; j < 8; j++) {
        const int k = lane + j * 32;
        if (k >= K) break;
        int d1, d0;
        digitize(vals[j] * inv, d1, d0);
        const size_t a = (size_t)(L * 2 + (k >> 7)) * 65536
                       + (size_t)(((n >> 3) * 8 + ((k >> 4) & 7)) * 128 + (n & 7) * 16 + (k & 15));
        gw[a] = (int8_t)d1;
        gw[a + 32768] = (int8_t)d0;
    }
    if (lane == 0) g_sb[id] = m * (1.0f / 16256.0f);
}

// ---------------- main fused decoder ----------------------------------------
__global__ void __launch_bounds__(NTH, 1)
decoder(const float* __restrict__ points,
        const float* __restrict__ b_in, const float* __restrict__ b_hid,
        const float* __restrict__ w_rgb, const float* __restrict__ b_rgb,
        const float* __restrict__ w_den, const float* __restrict__ b_den,
        const float* __restrict__ w_emb, const float* __restrict__ b_emb,
        float* __restrict__ out) {
    extern __shared__ char sm[];
    const uint32_t smb = smem_u32(sm);
    const int t = threadIdx.x, lane = t & 31, wid = t >> 5;
    const int wm = wid >> 2, wn = wid & 3;     // 4(M) x 4(N)
    const int g0 = blockIdx.x * PTS;
    const uint8_t* gw = (const uint8_t*)g_wq;

    // kick off weight chunk 0 (64KB; overlaps sampling)
    {
        const uint32_t dst = smb + SO_WBUF;
#pragma unroll
        for (int i = 0; i < 8; i++) {
            const int off = (t + i * NTH) * 16;
            CP_ASYNC16(dst + off, gw + off);
        }
        CP_COMMIT();
    }

    float* sbias = (float*)(sm + SO_SBIAS);
    float* sbs   = (float*)(sm + SO_SB);
    float* wht   = (float*)(sm + SO_WHT);
    float* rmax  = (float*)(sm + SO_RMAX);
    float* saA   = (float*)(sm + SO_SA);       // [2][64]
    float* invs  = (float*)(sm + SO_INV);
    int*   famax = (int*)(sm + SO_FAMAX);
    float* bhd   = (float*)(sm + SO_BHD);

    for (int i = t; i < 2560; i += NTH) {
        sbias[i] = (i < 256) ? b_in[i] : b_hid[i - 256];
        sbs[i] = g_sb[i] * 128.0f;            // pre-x128 for IMAD dequant form
    }
    for (int i = t; i < 256; i += NTH) {
        wht[i * 8 + 0] = w_rgb[i];        wht[i * 8 + 1] = w_rgb[256 + i];
        wht[i * 8 + 2] = w_rgb[512 + i];  wht[i * 8 + 3] = w_den[i];
        wht[i * 8 + 4] = w_emb[i];        wht[i * 8 + 5] = w_emb[256 + i];
        wht[i * 8 + 6] = w_emb[512 + i];  wht[i * 8 + 7] = 0.0f;
    }
    // zero BOTH A planes exactly (32KB; must NOT touch SO_WBUF — cp.async live)
    {
        uint4 z = {0u, 0u, 0u, 0u};
        uint4* ap = (uint4*)(sm + SO_A1);
#pragma unroll
        for (int i = 0; i < 4; i++) ap[t + i * NTH] = z;   // 2048 uint4 = 32KB
    }
    if (t < 64) famax[t] = 0;
    if (t < 3) bhd[t] = b_rgb[t];
    else if (t == 3) bhd[3] = b_den[0];
    else if (t < 7) bhd[t] = b_emb[t - 4];
    else if (t == 7) bhd[7] = 0.0f;
    __syncthreads();

    // ---- sampling phase A ---------------------------------------------------
    float frx[12], fry[12];
#pragma unroll
    for (int i = 0; i < 12; i++) {
        const int task = wid + i * 16;
        const int p = task / 3, pl = task - p * 3;
        const int g = g0 + p, b = g / NN;
        const float px = points[(size_t)g * 3 + 0];
        const float py = points[(size_t)g * 3 + 1];
        const float pz = points[(size_t)g * 3 + 2];
        float gx, gy;
        if (pl == 0)      { gx = px; gy = py; }
        else if (pl == 1) { gx = px; gy = pz; }
        else              { gx = py; gy = pz; }
        const float ix = (gx + 1.0f) * 0.5f * (float)(WW - 1);
        const float iy = (gy + 1.0f) * 0.5f * (float)(HH - 1);
        const float x0f = floorf(ix), y0f = floorf(iy);
        const float wx = ix - x0f, wy = iy - y0f;
        const int x0 = min(max((int)x0f, 0), WW - 1);
        const int x1 = min(max((int)x0f + 1, 0), WW - 1);
        const int y0 = min(max((int)y0f, 0), HH - 1);
        const int y1 = min(max((int)y0f + 1, 0), HH - 1);
        const float* base = g_trip + (size_t)(b * 3 + pl) * (HH * WW) * CC;
        const float2* c00 = (const float2*)(base + ((size_t)y0 * WW + x0) * CC);
        const float2* c01 = (const float2*)(base + ((size_t)y0 * WW + x1) * CC);
        const float2* c10 = (const float2*)(base + ((size_t)y1 * WW + x0) * CC);
        const float2* c11 = (const float2*)(base + ((size_t)y1 * WW + x1) * CC);
        const float w00 = (1.0f - wx) * (1.0f - wy), w01 = wx * (1.0f - wy);
        const float w10 = (1.0f - wx) * wy,          w11 = wx * wy;
        const float2 v00 = c00[lane], v01 = c01[lane];
        const float2 v10 = c10[lane], v11 = c11[lane];
        const float rx = v00.x * w00 + v01.x * w01 + v10.x * w10 + v11.x * w11;
        const float ry = v00.y * w00 + v01.y * w01 + v10.y * w10 + v11.y * w11;
        frx[i] = rx; fry[i] = ry;
        float am = fmaxf(fabsf(rx), fabsf(ry));
#pragma unroll
        for (int off = 16; off; off >>= 1) am = fmaxf(am, __shfl_xor_sync(0xFFFFFFFFu, am, off));
        if (lane == 0) atomicMax(&famax[p], __float_as_int(am));
    }
    __syncthreads();
    if (t < 64) {
        const float m = __int_as_float(famax[t]);
        saA[t] = m * (1.0f / 16256.0f);
        invs[t] = 16256.0f / fmaxf(m, 1e-20f);
    }
    __syncthreads();

    // ---- sampling phase B: digitize feats into A planes ---------------------
#pragma unroll
    for (int i = 0; i < 12; i++) {
        const int task = wid + i * 16;
        const int p = task / 3, pl = task - p * 3;
        const float inv = invs[p];
        int d1x, d0x, d1y, d0y;
        digitize(frx[i] * inv, d1x, d0x);
        digitize(fry[i] * inv, d1y, d0y);
        const int col0 = pl * 64 + 2 * lane;
        const uint32_t u = (uint32_t)(col0 >> 4);
        const uint32_t base = (uint32_t)p * 256 + ((u ^ (p & 7)) << 4) + (col0 & 15);
        *(uint16_t*)(sm + SO_A1 + base) = (uint16_t)(((d1y & 0xFF) << 8) | (d1x & 0xFF));
        *(uint16_t*)(sm + SO_A0 + base) = (uint16_t)(((d0y & 0xFF) << 8) | (d0x & 0xFF));
    }
    __syncthreads();

    // ---- 10 layers ----------------------------------------------------------
    int gc = 0;
    for (int L = 0; L < 10; L++) {
        int acc1[8][4], accm[8][4];
#pragma unroll
        for (int ni = 0; ni < 8; ni++)
#pragma unroll
            for (int j = 0; j < 4; j++) { acc1[ni][j] = 0; accm[ni][j] = 0; }

        for (int ch = 0; ch < 2; ch++) {
            CP_WAIT0();
            __syncthreads();
            const uint32_t wb = smb + SO_WBUF + (gc & 1) * 65536;
            const int nxt = gc + 1;
            // issue ALL of next chunk's prefetch up front: max completion cover
            if (nxt < NCHUNK_TOT) {
                const uint32_t pdst = smb + SO_WBUF + (nxt & 1) * 65536;
                const uint8_t* psrc = gw + (size_t)nxt * 65536;
#pragma unroll
                for (int i = 0; i < 8; i++) {
                    const int off = (t + i * NTH) * 16;
                    CP_ASYNC16(pdst + off, psrc + off);
                }
                CP_COMMIT();
            }
            const uint32_t tB = (uint32_t)(lane >> 3);
            const uint32_t rowB = (uint32_t)(lane & 7);

#pragma unroll
            for (int ks = 0; ks < 4; ks++) {
                uint32_t a1[4], a0[4];
                {
                    const uint32_t rA = (uint32_t)(wm * 16 + (lane & 15));
                    const uint32_t uu = (uint32_t)(ch * 8 + ks * 2 + (lane >> 4));
                    const uint32_t aoff = rA * 256 + ((uu ^ (rA & 7)) << 4);
                    ldsm4(a1, smb + SO_A1 + aoff);
                    ldsm4(a0, smb + SO_A0 + aoff);
                }
#pragma unroll
                for (int nt2 = 0; nt2 < 4; nt2++) {
                    const uint32_t blk = (uint32_t)((wn * 8 + nt2 * 2 + (tB >> 1)) * 8
                                                    + ks * 2 + (tB & 1));
                    const uint32_t boff = blk * 128 + rowB * 16;
                    uint32_t bh[4], bl[4];
                    ldsm4(bh, wb + boff);
                    ldsm4(bl, wb + 32768 + boff);
                    mma_s8(acc1[nt2 * 2],     a1, bh[0], bh[1]);
                    mma_s8(acc1[nt2 * 2 + 1], a1, bh[2], bh[3]);
                    mma_s8(accm[nt2 * 2],     a1, bl[0], bl[1]);
                    mma_s8(accm[nt2 * 2 + 1], a1, bl[2], bl[3]);
                    mma_s8(accm[nt2 * 2],     a0, bh[0], bh[1]);
                    mma_s8(accm[nt2 * 2 + 1], a0, bh[2], bh[3]);
                }
            }
            gc++;
        }

        const float* sbl = sbs + L * 256;     // pre-x128 weight scales
        const float* bl_ = sbias + L * 256;
        const float* sap = saA + (L & 1) * 64;
        const int r1 = wm * 16 + (lane >> 2);

        if (L < 9) {
            // pass 1: dequant via IMAD form, cache v in dead acc1 regs, row max
            float rmx0 = 0.0f, rmx1 = 0.0f;
            {
                const float s0 = sap[r1], s1 = sap[r1 + 8];
#pragma unroll
                for (int ni = 0; ni < 8; ni++) {
                    const int c0 = wn * 64 + ni * 8 + 2 * (lane & 3);
                    const float sf00 = s0 * sbl[c0], sf01 = s0 * sbl[c0 + 1];
                    const float sf10 = s1 * sbl[c0], sf11 = s1 * sbl[c0 + 1];
                    const float b0 = bl_[c0], b1 = bl_[c0 + 1];
                    const int k0 = acc1[ni][0] * 128 + accm[ni][0];
                    const int k1 = acc1[ni][1] * 128 + accm[ni][1];
                    const int k2 = acc1[ni][2] * 128 + accm[ni][2];
                    const int k3 = acc1[ni][3] * 128 + accm[ni][3];
                    const float v0 = fmaxf(fmaf((float)k0, sf00, b0), 0.0f);
                    const float v1 = fmaxf(fmaf((float)k1, sf01, b1), 0.0f);
                    const float v2 = fmaxf(fmaf((float)k2, sf10, b0), 0.0f);
                    const float v3 = fmaxf(fmaf((float)k3, sf11, b1), 0.0f);
                    acc1[ni][0] = __float_as_int(v0); acc1[ni][1] = __float_as_int(v1);
                    acc1[ni][2] = __float_as_int(v2); acc1[ni][3] = __float_as_int(v3);
                    rmx0 = fmaxf(rmx0, fmaxf(v0, v1));
                    rmx1 = fmaxf(rmx1, fmaxf(v2, v3));
                }
            }
#pragma unroll
            for (int d = 1; d <= 2; d <<= 1) {
                rmx0 = fmaxf(rmx0, __shfl_xor_sync(0xFFFFFFFFu, rmx0, d));
                rmx1 = fmaxf(rmx1, __shfl_xor_sync(0xFFFFFFFFu, rmx1, d));
            }
            if ((lane & 3) == 0) {
                rmax[r1 * 4 + wn] = rmx0;
                rmax[(r1 + 8) * 4 + wn] = rmx1;
            }
            __syncthreads();                   // the ONLY epilogue barrier
            if (t < 64) {
                const float mm = fmaxf(fmaxf(rmax[t * 4], rmax[t * 4 + 1]),
                                       fmaxf(rmax[t * 4 + 2], rmax[t * 4 + 3]));
                saA[((L + 1) & 1) * 64 + t] = mm * (1.0f / 16256.0f);
            }
            const float m0 = fmaxf(fmaxf(rmax[r1 * 4], rmax[r1 * 4 + 1]),
                                   fmaxf(rmax[r1 * 4 + 2], rmax[r1 * 4 + 3]));
            const float m1 = fmaxf(fmaxf(rmax[(r1 + 8) * 4], rmax[(r1 + 8) * 4 + 1]),
                                   fmaxf(rmax[(r1 + 8) * 4 + 2], rmax[(r1 + 8) * 4 + 3]));
            const float i0 = 16256.0f / fmaxf(m0, 1e-20f);
            const float i1 = 16256.0f / fmaxf(m1, 1e-20f);
            // pass 2: integer digitize cached v -> A planes (ordered by the
            // next chunk's start-sync before any ldsm of layer L+1)
#pragma unroll
            for (int ni = 0; ni < 8; ni++) {
                const int c0 = wn * 64 + ni * 8 + 2 * (lane & 3);
                int e0, g0i, e1, g1i, e2, g2i, e3, g3i;
                digitize(__int_as_float(acc1[ni][0]) * i0, e0, g0i);
                digitize(__int_as_float(acc1[ni][1]) * i0, e1, g1i);
                digitize(__int_as_float(acc1[ni][2]) * i1, e2, g2i);
                digitize(__int_as_float(acc1[ni][3]) * i1, e3, g3i);
                const uint32_t u = (uint32_t)(c0 >> 4);
                const uint32_t ba = (uint32_t)r1 * 256 + ((u ^ (r1 & 7)) << 4) + (c0 & 15);
                *(uint16_t*)(sm + SO_A1 + ba) = (uint16_t)(((e1 & 0xFF) << 8) | (e0 & 0xFF));
                *(uint16_t*)(sm + SO_A0 + ba) = (uint16_t)(((g1i & 0xFF) << 8) | (g0i & 0xFF));
                *(uint16_t*)(sm + SO_A1 + ba + 2048) = (uint16_t)(((e3 & 0xFF) << 8) | (e2 & 0xFF));
                *(uint16_t*)(sm + SO_A0 + ba + 2048) = (uint16_t)(((g3i & 0xFF) << 8) | (g2i & 0xFF));
            }
        } else {
            __syncthreads();                   // all A-plane ldsm reads done
            // final layer: dequant -> f32 acts at SO_ACT [64][256] (overlay)
            float* act = (float*)(sm + SO_ACT);
            const float s0 = sap[r1], s1 = sap[r1 + 8];
#pragma unroll
            for (int ni = 0; ni < 8; ni++) {
                const int c0 = wn * 64 + ni * 8 + 2 * (lane & 3);
                const float sf00 = s0 * sbl[c0], sf01 = s0 * sbl[c0 + 1];
                const float sf10 = s1 * sbl[c0], sf11 = s1 * sbl[c0 + 1];
                const float b0 = bl_[c0], b1 = bl_[c0 + 1];
                const int k0 = acc1[ni][0] * 128 + accm[ni][0];
                const int k1 = acc1[ni][1] * 128 + accm[ni][1];
                const int k2 = acc1[ni][2] * 128 + accm[ni][2];
                const int k3 = acc1[ni][3] * 128 + accm[ni][3];
                act[r1 * 256 + c0]           = fmaxf(fmaf((float)k0, sf00, b0), 0.0f);
                act[r1 * 256 + c0 + 1]       = fmaxf(fmaf((float)k1, sf01, b1), 0.0f);
                act[(r1 + 8) * 256 + c0]     = fmaxf(fmaf((float)k2, sf10, b0), 0.0f);
                act[(r1 + 8) * 256 + c0 + 1] = fmaxf(fmaf((float)k3, sf11, b1), 0.0f);
            }
            __syncthreads();                   // acts visible for heads
        }
    }

    // ---- heads --------------------------------------------------------------
    const float* hf = (const float*)(sm + SO_ACT);
    for (int task = wid; task < PTS * 7; task += 16) {
        const int p = task & 63;
        const int j = task >> 6;
        const float4* hp = (const float4*)(hf + p * 256);
        float s = 0.0f;
#pragma unroll
        for (int ii = 0; ii < 2; ii++) {
            const float4 hv = hp[lane + ii * 32];
            const int c0 = (lane + ii * 32) * 4;
            s += hv.x * wht[(c0 + 0) * 8 + j] + hv.y * wht[(c0 + 1) * 8 + j]
               + hv.z * wht[(c0 + 2) * 8 + j] + hv.w * wht[(c0 + 3) * 8 + j];
        }
#pragma unroll
        for (int off = 16; off; off >>= 1) s += __shfl_xor_sync(0xFFFFFFFFu, s, off);
        if (lane == 0) {
            s += bhd[j];
            const int g = g0 + p;
            if (j < 3)
                out[(size_t)g * 3 + j] = 1.0f / (1.0f + expf(-s));
            else if (j == 3)
                out[(size_t)BB * NN * 3 + g] = s;
            else
                out[(size_t)BB * NN * 4 + (size_t)g * 3 + (j - 4)] = s;
        }
    }
}

// ---------------------------------------------------------------------------
extern "C" void kernel_launch(void* const* d_in, const int* in_sizes, int n_in,
                              void* d_out, int out_size) {
    const float* triplane = (const float*)d_in[0];
    const float* points   = (const float*)d_in[1];
    const float* w_in     = (const float*)d_in[2];
    const float* b_in     = (const float*)d_in[3];
    const float* w_hid    = (const float*)d_in[4];
    const float* b_hid    = (const float*)d_in[5];
    const float* w_rgb    = (const float*)d_in[6];
    const float* b_rgb    = (const float*)d_in[7];
    const float* w_den    = (const float*)d_in[8];
    const float* b_den    = (const float*)d_in[9];
    const float* w_emb    = (const float*)d_in[10];
    const float* b_emb    = (const float*)d_in[11];
    float* out = (float*)d_out;

    transpose_trip<<<dim3((HH * WW) / 32, BB * 3), 256>>>(triplane);
    prep_weights<<<320, 256>>>(w_in, w_hid);

    cudaFuncSetAttribute(decoder, cudaFuncAttributeMaxDynamicSharedMemorySize, SMEM_TOT);
    decoder<<<(BB * NN) / PTS, NTH, SMEM_TOT>>>(
        points, b_in, b_hid, w_rgb, b_rgb, w_den, b_den, w_emb, b_emb, out);
}

// round 15
// speedup vs baseline: 2.2932x; 1.7365x over previous
#include <cuda_runtime.h>
#include <math.h>
#include <stdint.h>

// ---------------------------------------------------------------------------
// TriplaneDecoder via int8 double-digit mma.sync (m16n8k32.s8) — compute_100.
// x = s*(d1*128 + d0). D = sa*sb*(16384*S11 + 128*S1m), S1m = d1a.d0b+d0a.d1b.
// R14b (resubmit; R14 bench was an infra failure): LDS polish — epilogue
// scale/bias as float2 pairs; head weights laid out [8][256] for float4
// reads. Math and op order unchanged vs R13 (rel_err must stay 4.304271e-4).
// 16 warps 4Mx4N tile 16x64; 64KB double-buffered chunks (20 total).
// ---------------------------------------------------------------------------

#define BB 4
#define NN 100000
#define CC 64
#define HH 256
#define WW 256
#define PTS 64
#define NTH 512
#define NCHUNK_TOT 20     // 10 layers x 2 chunks x 64KB

// smem byte offsets
#define SO_A1    0        // A d1 plane: 64 x 256 s8 (16KB)
#define SO_A0    16384    // A d0 plane (16KB)
#define SO_WBUF  32768    // 2 x 64KB weight chunk buffers (d1 32KB | d0 32KB)
#define SO_ACT   0        // overlay (final f32 acts 64x256 = 64KB)
#define SO_SBIAS 163840   // biases 10*256 f32
#define SO_SB    174080   // weight col scales x128 10*256 f32
#define SO_WHT   184320   // head weights [8][256] f32
#define SO_RMAX  192512   // rowmax partials [64][4] f32
#define SO_SA    193536   // A row scales, ping-pong [2][64] f32
#define SO_INV   194048   // inv scale [64] f32 (sampling only)
#define SO_FAMAX 194304   // feat |max| bits [64] u32
#define SO_BHD   194560   // head biases [8]
#define SMEM_TOT 194592

__device__ float g_trip[(size_t)BB * 3 * HH * WW * CC];
__device__ uint4 g_wq[1310720 / 16];       // 20 x 64KB chunks (zero-init pads L0)
__device__ float g_sb[10 * 256];           // per-output weight scales

// ---- PTX helpers -----------------------------------------------------------
__device__ __forceinline__ uint32_t smem_u32(const void* p) {
    uint32_t a;
    asm("{ .reg .u64 t; cvta.to.shared.u64 t, %1; cvt.u32.u64 %0, t; }" : "=r"(a) : "l"(p));
    return a;
}
__device__ __forceinline__ void ldsm4(uint32_t* r, uint32_t a) {
    asm volatile("ldmatrix.sync.aligned.m8n8.x4.shared.b16 {%0,%1,%2,%3}, [%4];"
                 : "=r"(r[0]), "=r"(r[1]), "=r"(r[2]), "=r"(r[3]) : "r"(a));
}
__device__ __forceinline__ void mma_s8(int* c, const uint32_t* a, uint32_t b0, uint32_t b1) {
    asm volatile("mma.sync.aligned.m16n8k32.row.col.s32.s8.s8.s32 "
                 "{%0,%1,%2,%3}, {%4,%5,%6,%7}, {%8,%9}, {%0,%1,%2,%3};"
                 : "+r"(c[0]), "+r"(c[1]), "+r"(c[2]), "+r"(c[3])
                 : "r"(a[0]), "r"(a[1]), "r"(a[2]), "r"(a[3]), "r"(b0), "r"(b1));
}
#define CP_ASYNC16(dst, src) \
    asm volatile("cp.async.cg.shared.global [%0], [%1], 16;" :: "r"(dst), "l"(src))
#define CP_COMMIT() asm volatile("cp.async.commit_group;")
#define CP_WAIT0()  asm volatile("cp.async.wait_group 0;")

// integer digitize: qi in [-16256,16256] -> d1 in [-127,127], d0 in [-64,63]
__device__ __forceinline__ void digitize(float q, int& d1, int& d0) {
    const int qi = __float2int_rn(q);
    d1 = (qi + 64) >> 7;
    d0 = qi - (d1 << 7);
}

// ---------------- prolog 1: triplane [pl][C][HW] -> [pl][HW][C] -------------
__global__ void transpose_trip(const float* __restrict__ in) {
    __shared__ float s[64][33];
    const int plane = blockIdx.y;
    const int hw0 = blockIdx.x * 32;
    const float* ip = in + (size_t)plane * CC * HH * WW;
    float* op = g_trip + (size_t)plane * HH * WW * CC;
    const int t = threadIdx.x, l32 = t & 31, grp = t >> 5;
#pragma unroll
    for (int i = 0; i < 8; i++) {
        int c = grp + i * 8;
        s[c][l32] = ip[(size_t)c * (HH * WW) + hw0 + l32];
    }
    __syncthreads();
    const int c2 = t & 63, r0 = t >> 6;
#pragma unroll
    for (int j = 0; j < 8; j++) {
        int r = r0 + j * 4;
        op[(size_t)(hw0 + r) * CC + c2] = s[c2][r];
    }
}

// ---------------- prolog 2: weight quantization -----------------------------
__global__ void prep_weights(const float* __restrict__ w_in,
                             const float* __restrict__ w_hid) {
    const int lane = threadIdx.x & 31;
    const int id = blockIdx.x * 8 + (threadIdx.x >> 5);
    if (id >= 2560) return;
    const int L = id >> 8, n = id & 255;
    const int K = (L == 0) ? 192 : 256;
    float vals[8];
    float m = 0.0f;
#pragma unroll
    for (int j = 0; j < 8; j++) {
        const int k = lane + j * 32;
        float v = 0.0f;
        if (k < K)
            v = (L == 0) ? w_in[n * 192 + k] : w_hid[(size_t)(L - 1) * 65536 + n * 256 + k];
        vals[j] = v;
        m = fmaxf(m, fabsf(v));
    }
#pragma unroll
    for (int off = 16; off; off >>= 1) m = fmaxf(m, __shfl_xor_sync(0xFFFFFFFFu, m, off));
    const float inv = 16256.0f / fmaxf(m, 1e-30f);
    int8_t* gw = (int8_t*)g_wq;
#pragma unroll
    for (int j = 0; j < 8; j++) {
        const int k = lane + j * 32;
        if (k >= K) break;
        int d1, d0;
        digitize(vals[j] * inv, d1, d0);
        const size_t a = (size_t)(L * 2 + (k >> 7)) * 65536
                       + (size_t)(((n >> 3) * 8 + ((k >> 4) & 7)) * 128 + (n & 7) * 16 + (k & 15));
        gw[a] = (int8_t)d1;
        gw[a + 32768] = (int8_t)d0;
    }
    if (lane == 0) g_sb[id] = m * (1.0f / 16256.0f);
}

// ---------------- main fused decoder ----------------------------------------
__global__ void __launch_bounds__(NTH, 1)
decoder(const float* __restrict__ points,
        const float* __restrict__ b_in, const float* __restrict__ b_hid,
        const float* __restrict__ w_rgb, const float* __restrict__ b_rgb,
        const float* __restrict__ w_den, const float* __restrict__ b_den,
        const float* __restrict__ w_emb, const float* __restrict__ b_emb,
        float* __restrict__ out) {
    extern __shared__ char sm[];
    const uint32_t smb = smem_u32(sm);
    const int t = threadIdx.x, lane = t & 31, wid = t >> 5;
    const int wm = wid >> 2, wn = wid & 3;     // 4(M) x 4(N)
    const int g0 = blockIdx.x * PTS;
    const uint8_t* gw = (const uint8_t*)g_wq;

    // kick off weight chunk 0 (64KB; overlaps sampling)
    {
        const uint32_t dst = smb + SO_WBUF;
#pragma unroll
        for (int i = 0; i < 8; i++) {
            const int off = (t + i * NTH) * 16;
            CP_ASYNC16(dst + off, gw + off);
        }
        CP_COMMIT();
    }

    float* sbias = (float*)(sm + SO_SBIAS);
    float* sbs   = (float*)(sm + SO_SB);
    float* wht   = (float*)(sm + SO_WHT);      // [8][256]
    float* rmax  = (float*)(sm + SO_RMAX);
    float* saA   = (float*)(sm + SO_SA);       // [2][64]
    float* invs  = (float*)(sm + SO_INV);
    int*   famax = (int*)(sm + SO_FAMAX);
    float* bhd   = (float*)(sm + SO_BHD);

    for (int i = t; i < 2560; i += NTH) {
        sbias[i] = (i < 256) ? b_in[i] : b_hid[i - 256];
        sbs[i] = g_sb[i] * 128.0f;            // pre-x128 for IMAD dequant form
    }
    for (int i = t; i < 256; i += NTH) {
        wht[0 * 256 + i] = w_rgb[i];
        wht[1 * 256 + i] = w_rgb[256 + i];
        wht[2 * 256 + i] = w_rgb[512 + i];
        wht[3 * 256 + i] = w_den[i];
        wht[4 * 256 + i] = w_emb[i];
        wht[5 * 256 + i] = w_emb[256 + i];
        wht[6 * 256 + i] = w_emb[512 + i];
        wht[7 * 256 + i] = 0.0f;
    }
    // zero BOTH A planes exactly (32KB; must NOT touch SO_WBUF — cp.async live)
    {
        uint4 z = {0u, 0u, 0u, 0u};
        uint4* ap = (uint4*)(sm + SO_A1);
#pragma unroll
        for (int i = 0; i < 4; i++) ap[t + i * NTH] = z;   // 2048 uint4 = 32KB
    }
    if (t < 64) famax[t] = 0;
    if (t < 3) bhd[t] = b_rgb[t];
    else if (t == 3) bhd[3] = b_den[0];
    else if (t < 7) bhd[t] = b_emb[t - 4];
    else if (t == 7) bhd[7] = 0.0f;
    __syncthreads();

    // ---- sampling phase A ---------------------------------------------------
    float frx[12], fry[12];
#pragma unroll
    for (int i = 0; i < 12; i++) {
        const int task = wid + i * 16;
        const int p = task / 3, pl = task - p * 3;
        const int g = g0 + p, b = g / NN;
        const float px = points[(size_t)g * 3 + 0];
        const float py = points[(size_t)g * 3 + 1];
        const float pz = points[(size_t)g * 3 + 2];
        float gx, gy;
        if (pl == 0)      { gx = px; gy = py; }
        else if (pl == 1) { gx = px; gy = pz; }
        else              { gx = py; gy = pz; }
        const float ix = (gx + 1.0f) * 0.5f * (float)(WW - 1);
        const float iy = (gy + 1.0f) * 0.5f * (float)(HH - 1);
        const float x0f = floorf(ix), y0f = floorf(iy);
        const float wx = ix - x0f, wy = iy - y0f;
        const int x0 = min(max((int)x0f, 0), WW - 1);
        const int x1 = min(max((int)x0f + 1, 0), WW - 1);
        const int y0 = min(max((int)y0f, 0), HH - 1);
        const int y1 = min(max((int)y0f + 1, 0), HH - 1);
        const float* base = g_trip + (size_t)(b * 3 + pl) * (HH * WW) * CC;
        const float2* c00 = (const float2*)(base + ((size_t)y0 * WW + x0) * CC);
        const float2* c01 = (const float2*)(base + ((size_t)y0 * WW + x1) * CC);
        const float2* c10 = (const float2*)(base + ((size_t)y1 * WW + x0) * CC);
        const float2* c11 = (const float2*)(base + ((size_t)y1 * WW + x1) * CC);
        const float w00 = (1.0f - wx) * (1.0f - wy), w01 = wx * (1.0f - wy);
        const float w10 = (1.0f - wx) * wy,          w11 = wx * wy;
        const float2 v00 = c00[lane], v01 = c01[lane];
        const float2 v10 = c10[lane], v11 = c11[lane];
        const float rx = v00.x * w00 + v01.x * w01 + v10.x * w10 + v11.x * w11;
        const float ry = v00.y * w00 + v01.y * w01 + v10.y * w10 + v11.y * w11;
        frx[i] = rx; fry[i] = ry;
        float am = fmaxf(fabsf(rx), fabsf(ry));
#pragma unroll
        for (int off = 16; off; off >>= 1) am = fmaxf(am, __shfl_xor_sync(0xFFFFFFFFu, am, off));
        if (lane == 0) atomicMax(&famax[p], __float_as_int(am));
    }
    __syncthreads();
    if (t < 64) {
        const float m = __int_as_float(famax[t]);
        saA[t] = m * (1.0f / 16256.0f);
        invs[t] = 16256.0f / fmaxf(m, 1e-20f);
    }
    __syncthreads();

    // ---- sampling phase B: digitize feats into A planes ---------------------
#pragma unroll
    for (int i = 0; i < 12; i++) {
        const int task = wid + i * 16;
        const int p = task / 3, pl = task - p * 3;
        const float inv = invs[p];
        int d1x, d0x, d1y, d0y;
        digitize(frx[i] * inv, d1x, d0x);
        digitize(fry[i] * inv, d1y, d0y);
        const int col0 = pl * 64 + 2 * lane;
        const uint32_t u = (uint32_t)(col0 >> 4);
        const uint32_t base = (uint32_t)p * 256 + ((u ^ (p & 7)) << 4) + (col0 & 15);
        *(uint16_t*)(sm + SO_A1 + base) = (uint16_t)(((d1y & 0xFF) << 8) | (d1x & 0xFF));
        *(uint16_t*)(sm + SO_A0 + base) = (uint16_t)(((d0y & 0xFF) << 8) | (d0x & 0xFF));
    }
    __syncthreads();

    // ---- 10 layers ----------------------------------------------------------
    int gc = 0;
    for (int L = 0; L < 10; L++) {
        int acc1[8][4], accm[8][4];
#pragma unroll
        for (int ni = 0; ni < 8; ni++)
#pragma unroll
            for (int j = 0; j < 4; j++) { acc1[ni][j] = 0; accm[ni][j] = 0; }

        for (int ch = 0; ch < 2; ch++) {
            CP_WAIT0();
            __syncthreads();
            const uint32_t wb = smb + SO_WBUF + (gc & 1) * 65536;
            const int nxt = gc + 1;
            // issue ALL of next chunk's prefetch up front: max completion cover
            if (nxt < NCHUNK_TOT) {
                const uint32_t pdst = smb + SO_WBUF + (nxt & 1) * 65536;
                const uint8_t* psrc = gw + (size_t)nxt * 65536;
#pragma unroll
                for (int i = 0; i < 8; i++) {
                    const int off = (t + i * NTH) * 16;
                    CP_ASYNC16(pdst + off, psrc + off);
                }
                CP_COMMIT();
            }
            const uint32_t tB = (uint32_t)(lane >> 3);
            const uint32_t rowB = (uint32_t)(lane & 7);

#pragma unroll
            for (int ks = 0; ks < 4; ks++) {
                uint32_t a1[4], a0[4];
                {
                    const uint32_t rA = (uint32_t)(wm * 16 + (lane & 15));
                    const uint32_t uu = (uint32_t)(ch * 8 + ks * 2 + (lane >> 4));
                    const uint32_t aoff = rA * 256 + ((uu ^ (rA & 7)) << 4);
                    ldsm4(a1, smb + SO_A1 + aoff);
                    ldsm4(a0, smb + SO_A0 + aoff);
                }
#pragma unroll
                for (int nt2 = 0; nt2 < 4; nt2++) {
                    const uint32_t blk = (uint32_t)((wn * 8 + nt2 * 2 + (tB >> 1)) * 8
                                                    + ks * 2 + (tB & 1));
                    const uint32_t boff = blk * 128 + rowB * 16;
                    uint32_t bh[4], bl[4];
                    ldsm4(bh, wb + boff);
                    ldsm4(bl, wb + 32768 + boff);
                    mma_s8(acc1[nt2 * 2],     a1, bh[0], bh[1]);
                    mma_s8(acc1[nt2 * 2 + 1], a1, bh[2], bh[3]);
                    mma_s8(accm[nt2 * 2],     a1, bl[0], bl[1]);
                    mma_s8(accm[nt2 * 2 + 1], a1, bl[2], bl[3]);
                    mma_s8(accm[nt2 * 2],     a0, bh[0], bh[1]);
                    mma_s8(accm[nt2 * 2 + 1], a0, bh[2], bh[3]);
                }
            }
            gc++;
        }

        const float2* sbl2 = (const float2*)(sbs + L * 256);
        const float2* bl2  = (const float2*)(sbias + L * 256);
        const float* sap = saA + (L & 1) * 64;
        const int r1 = wm * 16 + (lane >> 2);

        if (L < 9) {
            // pass 1: dequant via IMAD form, cache v in dead acc1 regs, row max
            float rmx0 = 0.0f, rmx1 = 0.0f;
            {
                const float s0 = sap[r1], s1 = sap[r1 + 8];
#pragma unroll
                for (int ni = 0; ni < 8; ni++) {
                    const int c0 = wn * 64 + ni * 8 + 2 * (lane & 3);
                    const float2 sf = sbl2[c0 >> 1];
                    const float2 bb = bl2[c0 >> 1];
                    const float sf00 = s0 * sf.x, sf01 = s0 * sf.y;
                    const float sf10 = s1 * sf.x, sf11 = s1 * sf.y;
                    const int k0 = acc1[ni][0] * 128 + accm[ni][0];
                    const int k1 = acc1[ni][1] * 128 + accm[ni][1];
                    const int k2 = acc1[ni][2] * 128 + accm[ni][2];
                    const int k3 = acc1[ni][3] * 128 + accm[ni][3];
                    const float v0 = fmaxf(fmaf((float)k0, sf00, bb.x), 0.0f);
                    const float v1 = fmaxf(fmaf((float)k1, sf01, bb.y), 0.0f);
                    const float v2 = fmaxf(fmaf((float)k2, sf10, bb.x), 0.0f);
                    const float v3 = fmaxf(fmaf((float)k3, sf11, bb.y), 0.0f);
                    acc1[ni][0] = __float_as_int(v0); acc1[ni][1] = __float_as_int(v1);
                    acc1[ni][2] = __float_as_int(v2); acc1[ni][3] = __float_as_int(v3);
                    rmx0 = fmaxf(rmx0, fmaxf(v0, v1));
                    rmx1 = fmaxf(rmx1, fmaxf(v2, v3));
                }
            }
#pragma unroll
            for (int d = 1; d <= 2; d <<= 1) {
                rmx0 = fmaxf(rmx0, __shfl_xor_sync(0xFFFFFFFFu, rmx0, d));
                rmx1 = fmaxf(rmx1, __shfl_xor_sync(0xFFFFFFFFu, rmx1, d));
            }
            if ((lane & 3) == 0) {
                rmax[r1 * 4 + wn] = rmx0;
                rmax[(r1 + 8) * 4 + wn] = rmx1;
            }
            __syncthreads();                   // the ONLY epilogue barrier
            if (t < 64) {
                const float mm = fmaxf(fmaxf(rmax[t * 4], rmax[t * 4 + 1]),
                                       fmaxf(rmax[t * 4 + 2], rmax[t * 4 + 3]));
                saA[((L + 1) & 1) * 64 + t] = mm * (1.0f / 16256.0f);
            }
            const float m0 = fmaxf(fmaxf(rmax[r1 * 4], rmax[r1 * 4 + 1]),
                                   fmaxf(rmax[r1 * 4 + 2], rmax[r1 * 4 + 3]));
            const float m1 = fmaxf(fmaxf(rmax[(r1 + 8) * 4], rmax[(r1 + 8) * 4 + 1]),
                                   fmaxf(rmax[(r1 + 8) * 4 + 2], rmax[(r1 + 8) * 4 + 3]));
            const float i0 = 16256.0f / fmaxf(m0, 1e-20f);
            const float i1 = 16256.0f / fmaxf(m1, 1e-20f);
            // pass 2: integer digitize cached v -> A planes (ordered by the
            // next chunk's start-sync before any ldsm of layer L+1)
#pragma unroll
            for (int ni = 0; ni < 8; ni++) {
                const int c0 = wn * 64 + ni * 8 + 2 * (lane & 3);
                int e0, g0i, e1, g1i, e2, g2i, e3, g3i;
                digitize(__int_as_float(acc1[ni][0]) * i0, e0, g0i);
                digitize(__int_as_float(acc1[ni][1]) * i0, e1, g1i);
                digitize(__int_as_float(acc1[ni][2]) * i1, e2, g2i);
                digitize(__int_as_float(acc1[ni][3]) * i1, e3, g3i);
                const uint32_t u = (uint32_t)(c0 >> 4);
                const uint32_t ba = (uint32_t)r1 * 256 + ((u ^ (r1 & 7)) << 4) + (c0 & 15);
                *(uint16_t*)(sm + SO_A1 + ba) = (uint16_t)(((e1 & 0xFF) << 8) | (e0 & 0xFF));
                *(uint16_t*)(sm + SO_A0 + ba) = (uint16_t)(((g1i & 0xFF) << 8) | (g0i & 0xFF));
                *(uint16_t*)(sm + SO_A1 + ba + 2048) = (uint16_t)(((e3 & 0xFF) << 8) | (e2 & 0xFF));
                *(uint16_t*)(sm + SO_A0 + ba + 2048) = (uint16_t)(((g3i & 0xFF) << 8) | (g2i & 0xFF));
            }
        } else {
            __syncthreads();                   // all A-plane ldsm reads done
            // final layer: dequant -> f32 acts at SO_ACT [64][256] (overlay)
            float* act = (float*)(sm + SO_ACT);
            const float s0 = sap[r1], s1 = sap[r1 + 8];
#pragma unroll
            for (int ni = 0; ni < 8; ni++) {
                const int c0 = wn * 64 + ni * 8 + 2 * (lane & 3);
                const float2 sf = sbl2[c0 >> 1];
                const float2 bb = bl2[c0 >> 1];
                const float sf00 = s0 * sf.x, sf01 = s0 * sf.y;
                const float sf10 = s1 * sf.x, sf11 = s1 * sf.y;
                const int k0 = acc1[ni][0] * 128 + accm[ni][0];
                const int k1 = acc1[ni][1] * 128 + accm[ni][1];
                const int k2 = acc1[ni][2] * 128 + accm[ni][2];
                const int k3 = acc1[ni][3] * 128 + accm[ni][3];
                act[r1 * 256 + c0]           = fmaxf(fmaf((float)k0, sf00, bb.x), 0.0f);
                act[r1 * 256 + c0 + 1]       = fmaxf(fmaf((float)k1, sf01, bb.y), 0.0f);
                act[(r1 + 8) * 256 + c0]     = fmaxf(fmaf((float)k2, sf10, bb.x), 0.0f);
                act[(r1 + 8) * 256 + c0 + 1] = fmaxf(fmaf((float)k3, sf11, bb.y), 0.0f);
            }
            __syncthreads();                   // acts visible for heads
        }
    }

    // ---- heads (wht laid out [j][256] -> contiguous float4 reads) -----------
    const float* hf = (const float*)(sm + SO_ACT);
    for (int task = wid; task < PTS * 7; task += 16) {
        const int p = task & 63;
        const int j = task >> 6;
        const float4* hp = (const float4*)(hf + p * 256);
        const float4* wp = (const float4*)(wht + j * 256);
        float s = 0.0f;
#pragma unroll
        for (int ii = 0; ii < 2; ii++) {
            const float4 hv = hp[lane + ii * 32];
            const float4 wv = wp[lane + ii * 32];
            s += hv.x * wv.x + hv.y * wv.y + hv.z * wv.z + hv.w * wv.w;
        }
#pragma unroll
        for (int off = 16; off; off >>= 1) s += __shfl_xor_sync(0xFFFFFFFFu, s, off);
        if (lane == 0) {
            s += bhd[j];
            const int g = g0 + p;
            if (j < 3)
                out[(size_t)g * 3 + j] = 1.0f / (1.0f + expf(-s));
            else if (j == 3)
                out[(size_t)BB * NN * 3 + g] = s;
            else
                out[(size_t)BB * NN * 4 + (size_t)g * 3 + (j - 4)] = s;
        }
    }
}

// ---------------------------------------------------------------------------
extern "C" void kernel_launch(void* const* d_in, const int* in_sizes, int n_in,
                              void* d_out, int out_size) {
    const float* triplane = (const float*)d_in[0];
    const float* points   = (const float*)d_in[1];
    const float* w_in     = (const float*)d_in[2];
    const float* b_in     = (const float*)d_in[3];
    const float* w_hid    = (const float*)d_in[4];
    const float* b_hid    = (const float*)d_in[5];
    const float* w_rgb    = (const float*)d_in[6];
    const float* b_rgb    = (const float*)d_in[7];
    const float* w_den    = (const float*)d_in[8];
    const float* b_den    = (const float*)d_in[9];
    const float* w_emb    = (const float*)d_in[10];
    const float* b_emb    = (const float*)d_in[11];
    float* out = (float*)d_out;

    transpose_trip<<<dim3((HH * WW) / 32, BB * 3), 256>>>(triplane);
    prep_weights<<<320, 256>>>(w_in, w_hid);

    cudaFuncSetAttribute(decoder, cudaFuncAttributeMaxDynamicSharedMemorySize, SMEM_TOT);
    decoder<<<(BB * NN) / PTS, NTH, SMEM_TOT>>>(
        points, b_in, b_hid, w_rgb, b_rgb, w_den, b_den, w_emb, b_emb, out);
}